// round 2
// baseline (speedup 1.0000x reference)
#include <cuda_runtime.h>
#include <cstdint>
#include <cmath>

// 134 MB scratch for the mid tensor x [4,128,256,256]
static __device__ float g_xmid[(size_t)4 * 128 * 256 * 256];

// ---------------------------------------------------------------------------
// 8-point complex FFT, decimation-in-time. s = +1: forward (e^{-i}), s = -1:
// inverse (e^{+i}), NO scaling. Fully unrolled, register-resident.
// ---------------------------------------------------------------------------
__device__ __forceinline__ void cfft8(float zr[8], float zi[8], const float s)
{
    const float cc = 0.70710678118654752440f;
    // even half: z0,z2,z4,z6
    float t0r = zr[0] + zr[4], t0i = zi[0] + zi[4];
    float t1r = zr[0] - zr[4], t1i = zi[0] - zi[4];
    float t2r = zr[2] + zr[6], t2i = zi[2] + zi[6];
    float t3r = zr[2] - zr[6], t3i = zi[2] - zi[6];
    float E0r = t0r + t2r, E0i = t0i + t2i;
    float E2r = t0r - t2r, E2i = t0i - t2i;
    float E1r = t1r + s * t3i, E1i = t1i - s * t3r;
    float E3r = t1r - s * t3i, E3i = t1i + s * t3r;
    // odd half: z1,z3,z5,z7
    float u0r = zr[1] + zr[5], u0i = zi[1] + zi[5];
    float u1r = zr[1] - zr[5], u1i = zi[1] - zi[5];
    float u2r = zr[3] + zr[7], u2i = zi[3] + zi[7];
    float u3r = zr[3] - zr[7], u3i = zi[3] - zi[7];
    float O0r = u0r + u2r, O0i = u0i + u2i;
    float O2r = u0r - u2r, O2i = u0i - u2i;
    float O1r = u1r + s * u3i, O1i = u1i - s * u3r;
    float O3r = u1r - s * u3i, O3i = u1i + s * u3r;
    // twiddles W8^{sk}
    float T0r = O0r, T0i = O0i;
    float T1r = cc * (O1r + s * O1i), T1i = cc * (O1i - s * O1r);
    float T2r = s * O2i,              T2i = -s * O2r;
    float T3r = cc * (s * O3i - O3r), T3i = -cc * (O3i + s * O3r);
    zr[0] = E0r + T0r; zi[0] = E0i + T0i;
    zr[4] = E0r - T0r; zi[4] = E0i - T0i;
    zr[1] = E1r + T1r; zi[1] = E1i + T1i;
    zr[5] = E1r - T1r; zi[5] = E1i - T1i;
    zr[2] = E2r + T2r; zi[2] = E2i + T2i;
    zr[6] = E2r - T2r; zi[6] = E2i - T2i;
    zr[3] = E3r + T3r; zi[3] = E3i + T3i;
    zr[7] = E3r - T3r; zi[7] = E3i - T3i;
}

// rfft2 of an 8x8 real patch (x[r*8+c], contiguous). Output: half spectrum
// F[u][v], u=0..7, v=0..4 stored at index u*5+v.
__device__ __forceinline__ void rfft2_8x8(const float* __restrict__ x,
                                          float Fr[40], float Fi[40])
{
    // rows: rfft along last axis (keep v = 0..4)
#pragma unroll
    for (int r = 0; r < 8; r++) {
        float zr[8], zi[8];
#pragma unroll
        for (int c = 0; c < 8; c++) { zr[c] = x[r * 8 + c]; zi[c] = 0.f; }
        cfft8(zr, zi, 1.0f);
#pragma unroll
        for (int v = 0; v < 5; v++) { Fr[r * 5 + v] = zr[v]; Fi[r * 5 + v] = zi[v]; }
    }
    // columns: full complex fft along axis -2
#pragma unroll
    for (int v = 0; v < 5; v++) {
        float zr[8], zi[8];
#pragma unroll
        for (int u = 0; u < 8; u++) { zr[u] = Fr[u * 5 + v]; zi[u] = Fi[u * 5 + v]; }
        cfft8(zr, zi, 1.0f);
#pragma unroll
        for (int u = 0; u < 8; u++) { Fr[u * 5 + v] = zr[u]; Fi[u * 5 + v] = zi[u]; }
    }
}

// ---------------------------------------------------------------------------
// Kernel F: per patch (b, ph, pw): 1x1 convs (GEMM 256x64, k=64) + forward
// FFTs + filter + combine + inverse FFT; writes un-patched x to g_xmid.
// smem (floats):
//   [0,16384)      sWT  [64][256]  weights transposed (img | event)
//   [16384,24576)  sIn  [2][64][64] pixels
//   [24576,41216)  sMid [256][65]  GEMM results (padded rows)
//   [41216,46464)  sFilt[128][41]
//   sFFT [256][81] aliases [0,20736) after the GEMM phase.
// ---------------------------------------------------------------------------
__global__ void __launch_bounds__(256) kF(const float* __restrict__ img,
                                          const float* __restrict__ evt,
                                          const float* __restrict__ w_img,
                                          const float* __restrict__ w_evt,
                                          const float* __restrict__ filt)
{
    extern __shared__ float sm[];
    float* sWT   = sm;            // [64][256]
    float* sIn   = sm + 16384;    // [2][64][64]
    float* sMid  = sm + 24576;    // [256][65]
    float* sFilt = sm + 41216;    // [128][41]
    float* sFFT  = sm;            // [256][81], reuses sWT+sIn region

    const int tid = threadIdx.x;
    const int pw = blockIdx.x, ph = blockIdx.y, b = blockIdx.z;

    // load weights transposed: sWT[k][o] (o<128: img, o>=128: event)
    for (int i = tid; i < 64 * 128; i += 256) {
        int k = i >> 7, o = i & 127;
        sWT[k * 256 + o]       = w_img[o * 64 + k];
        sWT[k * 256 + 128 + o] = w_evt[o * 64 + k];
    }
    // filter [128][40] -> padded [128][41]
    for (int i = tid; i < 128 * 40; i += 256) {
        int o = i / 40, j = i - o * 40;
        sFilt[o * 41 + j] = filt[i];
    }
    // patch pixels: 64 channels x 64 px, float4 loads
    {
        const float4* img4 = reinterpret_cast<const float4*>(img);
        const float4* evt4 = reinterpret_cast<const float4*>(evt);
        for (int i = tid; i < 64 * 16; i += 256) {
            int c = i >> 4, q = i & 15;
            int r = q >> 1, h = q & 1;
            int g4 = (((b * 64 + c) * 256 + ph * 8 + r) * 256 + pw * 8) / 4 + h;
            float4 v0 = img4[g4];
            float4 v1 = evt4[g4];
            *reinterpret_cast<float4*>(&sIn[c * 64 + q * 4])        = v0;
            *reinterpret_cast<float4*>(&sIn[4096 + c * 64 + q * 4]) = v1;
        }
    }
    __syncthreads();

    // GEMM: rows 0..255 (channel slots) x cols 0..63 (pixels), k = 64
    {
        int rb = tid >> 3, cb = tid & 7;
        int r0 = rb * 8, c0 = cb * 8;
        const float* pin = sIn + ((r0 >= 128) ? 4096 : 0);
        float acc[64];
#pragma unroll
        for (int i = 0; i < 64; i++) acc[i] = 0.f;
#pragma unroll 4
        for (int k = 0; k < 64; k++) {
            float4 w0 = *reinterpret_cast<const float4*>(&sWT[k * 256 + r0]);
            float4 w1 = *reinterpret_cast<const float4*>(&sWT[k * 256 + r0 + 4]);
            float4 x0 = *reinterpret_cast<const float4*>(&pin[k * 64 + c0]);
            float4 x1 = *reinterpret_cast<const float4*>(&pin[k * 64 + c0 + 4]);
            float wv[8] = {w0.x, w0.y, w0.z, w0.w, w1.x, w1.y, w1.z, w1.w};
            float xv[8] = {x0.x, x0.y, x0.z, x0.w, x1.x, x1.y, x1.z, x1.w};
#pragma unroll
            for (int i = 0; i < 8; i++)
#pragma unroll
                for (int j = 0; j < 8; j++)
                    acc[i * 8 + j] = fmaf(wv[i], xv[j], acc[i * 8 + j]);
        }
#pragma unroll
        for (int i = 0; i < 8; i++)
#pragma unroll
            for (int j = 0; j < 8; j++)
                sMid[(r0 + i) * 65 + c0 + j] = acc[i * 8 + j];
    }
    __syncthreads();   // after this, sWT/sIn region is reusable as sFFT

    // forward FFTs: threads 0..127 -> event (with filter), 128..255 -> img
    {
        int o = tid & 127;
        bool isEvt = (tid < 128);
        const float* src = sMid + (isEvt ? (128 + o) : o) * 65;
        float Fr[40], Fi[40];
        rfft2_8x8(src, Fr, Fi);
        if (isEvt) {
#pragma unroll
            for (int j = 0; j < 40; j++) {
                float f = sFilt[o * 41 + j];
                Fr[j] *= f; Fi[j] *= f;
            }
        }
        float* dst = sFFT + (isEvt ? o : (128 + o)) * 81;
#pragma unroll
        for (int j = 0; j < 40; j++) { dst[j] = Fr[j]; dst[40 + j] = Fi[j]; }
    }
    __syncthreads();

    // combine + inverse (threads 0..127, one channel each)
    if (tid < 128) {
        int o = tid;
        const float* ev = sFFT + o * 81;
        const float* im = sFFT + (128 + o) * 81;
        float Xr[40], Xi[40];
#pragma unroll
        for (int j = 0; j < 40; j++) {
            float er = ev[j], ei = ev[40 + j];
            float ir = im[j] + 1.0f, ii = im[40 + j];
            Xr[j] = ir * er - ii * ei;
            Xi[j] = ir * ei + ii * er;
        }
        // inverse fft along columns (axis -2)
#pragma unroll
        for (int v = 0; v < 5; v++) {
            float zr[8], zi[8];
#pragma unroll
            for (int u = 0; u < 8; u++) { zr[u] = Xr[u * 5 + v]; zi[u] = Xi[u * 5 + v]; }
            cfft8(zr, zi, -1.0f);
#pragma unroll
            for (int u = 0; u < 8; u++) { Xr[u * 5 + v] = zr[u]; Xi[u * 5 + v] = zi[u]; }
        }
        // irfft along rows (hermitian extension; real part only), scale 1/64
        float* outp = g_xmid + (((size_t)(b * 128 + o) * 256 + ph * 8) * 256 + pw * 8);
        const float sc = 1.0f / 64.0f;
#pragma unroll
        for (int r = 0; r < 8; r++) {
            float zr[8], zi[8];
#pragma unroll
            for (int v = 0; v < 5; v++) { zr[v] = Xr[r * 5 + v]; zi[v] = Xi[r * 5 + v]; }
            zr[5] = Xr[r * 5 + 3]; zi[5] = -Xi[r * 5 + 3];
            zr[6] = Xr[r * 5 + 2]; zi[6] = -Xi[r * 5 + 2];
            zr[7] = Xr[r * 5 + 1]; zi[7] = -Xi[r * 5 + 1];
            cfft8(zr, zi, -1.0f);
            float4 o0 = {zr[0] * sc, zr[1] * sc, zr[2] * sc, zr[3] * sc};
            float4 o1 = {zr[4] * sc, zr[5] * sc, zr[6] * sc, zr[7] * sc};
            *reinterpret_cast<float4*>(&outp[r * 256])     = o0;
            *reinterpret_cast<float4*>(&outp[r * 256 + 4]) = o1;
        }
    }
}

// ---------------------------------------------------------------------------
// Kernel D: 16x16 output tile per block. Depthwise 3x3 (SAME, zero pad) on
// channels c and c+64, exact GELU gate, then 64x64 out 1x1 GEMM.
// smem (floats): sG[64][256]=16384 | sWoT[64][64]=4096 | sWdw[1152] | sHalo[2][18][20]=720
// ---------------------------------------------------------------------------
__global__ void __launch_bounds__(256) kD(const float* __restrict__ w_dw,
                                          const float* __restrict__ w_out,
                                          float* __restrict__ out)
{
    extern __shared__ float sm[];
    float* sG    = sm;           // [64][256]
    float* sWoT  = sm + 16384;   // [64][64] transposed: sWoT[k][o]
    float* sWdw  = sm + 20480;   // [128][9]
    float* sHalo = sm + 21632;   // [2][18][20]

    const int tid = threadIdx.x;
    const int bx = blockIdx.x, by = blockIdx.y, b = blockIdx.z;
    const int x0 = bx * 16, y0 = by * 16;

    for (int i = tid; i < 64 * 64; i += 256) {
        int k = i >> 6, o = i & 63;
        sWoT[k * 64 + o] = w_out[o * 64 + k];
    }
    for (int i = tid; i < 128 * 9; i += 256) sWdw[i] = w_dw[i];

    const int py = tid >> 4, px = tid & 15;
    const size_t cbase = (size_t)b * 128 * 65536;

    for (int c = 0; c < 64; c++) {
        __syncthreads();  // protect sHalo reuse (also covers sWdw on iter 0)
        for (int i = tid; i < 324; i += 256) {
            int y = i / 18, x = i - y * 18;
            int gy = y0 + y - 1, gx = x0 + x - 1;
            float v0 = 0.f, v1 = 0.f;
            if (gy >= 0 && gy < 256 && gx >= 0 && gx < 256) {
                size_t gi = cbase + (size_t)c * 65536 + (size_t)gy * 256 + gx;
                v0 = g_xmid[gi];
                v1 = g_xmid[gi + (size_t)64 * 65536];
            }
            sHalo[y * 20 + x]       = v0;
            sHalo[360 + y * 20 + x] = v1;
        }
        __syncthreads();
        float a = 0.f, bb = 0.f;
#pragma unroll
        for (int dy = 0; dy < 3; dy++)
#pragma unroll
            for (int dx = 0; dx < 3; dx++) {
                float w1 = sWdw[c * 9 + dy * 3 + dx];
                float w2 = sWdw[(c + 64) * 9 + dy * 3 + dx];
                a  = fmaf(sHalo[(py + dy) * 20 + px + dx],       w1, a);
                bb = fmaf(sHalo[360 + (py + dy) * 20 + px + dx], w2, bb);
            }
        float gl = 0.5f * a * (1.0f + erff(a * 0.70710678118654752f));
        sG[c * 256 + tid] = gl * bb;
    }
    __syncthreads();

    // out GEMM: 64 oc x 256 px, k = 64; per thread 8 oc x 8 px
    int ob = tid >> 5, pb = tid & 31;
    int oc0 = ob * 8, p0 = pb * 8;
    float acc[64];
#pragma unroll
    for (int i = 0; i < 64; i++) acc[i] = 0.f;
#pragma unroll 4
    for (int k = 0; k < 64; k++) {
        float4 w0 = *reinterpret_cast<const float4*>(&sWoT[k * 64 + oc0]);
        float4 w1 = *reinterpret_cast<const float4*>(&sWoT[k * 64 + oc0 + 4]);
        float4 g0 = *reinterpret_cast<const float4*>(&sG[k * 256 + p0]);
        float4 g1 = *reinterpret_cast<const float4*>(&sG[k * 256 + p0 + 4]);
        float wv[8] = {w0.x, w0.y, w0.z, w0.w, w1.x, w1.y, w1.z, w1.w};
        float gv[8] = {g0.x, g0.y, g0.z, g0.w, g1.x, g1.y, g1.z, g1.w};
#pragma unroll
        for (int i = 0; i < 8; i++)
#pragma unroll
            for (int j = 0; j < 8; j++)
                acc[i * 8 + j] = fmaf(wv[i], gv[j], acc[i * 8 + j]);
    }
    // write: each 8-px group is a half row of the 16x16 tile
    int wy = y0 + (p0 >> 4);
    int wx = x0 + (p0 & 15);
#pragma unroll
    for (int i = 0; i < 8; i++) {
        size_t ga = ((size_t)(b * 64 + oc0 + i) * 256 + wy) * 256 + wx;
        float4 q0 = {acc[i * 8 + 0], acc[i * 8 + 1], acc[i * 8 + 2], acc[i * 8 + 3]};
        float4 q1 = {acc[i * 8 + 4], acc[i * 8 + 5], acc[i * 8 + 6], acc[i * 8 + 7]};
        *reinterpret_cast<float4*>(&out[ga])     = q0;
        *reinterpret_cast<float4*>(&out[ga + 4]) = q1;
    }
}

// ---------------------------------------------------------------------------
extern "C" void kernel_launch(void* const* d_in, const int* in_sizes, int n_in,
                              void* d_out, int out_size)
{
    const float* img   = (const float*)d_in[0];
    const float* evt   = (const float*)d_in[1];
    const float* w_img = (const float*)d_in[2];
    const float* w_evt = (const float*)d_in[3];
    const float* w_dw  = (const float*)d_in[4];
    const float* filt  = (const float*)d_in[5];
    const float* w_out = (const float*)d_in[6];
    float* out = (float*)d_out;

    const int smemF = 46464 * 4;  // 185,856 B
    const int smemD = 22352 * 4;  //  89,408 B
    cudaFuncSetAttribute(kF, cudaFuncAttributeMaxDynamicSharedMemorySize, smemF);
    cudaFuncSetAttribute(kD, cudaFuncAttributeMaxDynamicSharedMemorySize, smemD);

    kF<<<dim3(32, 32, 4), 256, smemF>>>(img, evt, w_img, w_evt, filt);
    kD<<<dim3(16, 16, 4), 256, smemD>>>(w_dw, w_out, out);
}

// round 3
// speedup vs baseline: 1.0007x; 1.0007x over previous
#include <cuda_runtime.h>
#include <cstdint>
#include <cmath>

// 134 MB scratch for the mid tensor x [4,128,256,256]
static __device__ float g_xmid[(size_t)4 * 128 * 256 * 256];

// ---------------------------------------------------------------------------
// 8-point complex FFT, decimation-in-time. s = +1: forward (e^{-i}), s = -1:
// inverse (e^{+i}), NO scaling. Fully unrolled, register-resident.
// ---------------------------------------------------------------------------
__device__ __forceinline__ void cfft8(float zr[8], float zi[8], const float s)
{
    const float cc = 0.70710678118654752440f;
    // even half: z0,z2,z4,z6
    float t0r = zr[0] + zr[4], t0i = zi[0] + zi[4];
    float t1r = zr[0] - zr[4], t1i = zi[0] - zi[4];
    float t2r = zr[2] + zr[6], t2i = zi[2] + zi[6];
    float t3r = zr[2] - zr[6], t3i = zi[2] - zi[6];
    float E0r = t0r + t2r, E0i = t0i + t2i;
    float E2r = t0r - t2r, E2i = t0i - t2i;
    float E1r = t1r + s * t3i, E1i = t1i - s * t3r;
    float E3r = t1r - s * t3i, E3i = t1i + s * t3r;
    // odd half: z1,z3,z5,z7
    float u0r = zr[1] + zr[5], u0i = zi[1] + zi[5];
    float u1r = zr[1] - zr[5], u1i = zi[1] - zi[5];
    float u2r = zr[3] + zr[7], u2i = zi[3] + zi[7];
    float u3r = zr[3] - zr[7], u3i = zi[3] - zi[7];
    float O0r = u0r + u2r, O0i = u0i + u2i;
    float O2r = u0r - u2r, O2i = u0i - u2i;
    float O1r = u1r + s * u3i, O1i = u1i - s * u3r;
    float O3r = u1r - s * u3i, O3i = u1i + s * u3r;
    // twiddles W8^{sk}
    float T0r = O0r, T0i = O0i;
    float T1r = cc * (O1r + s * O1i), T1i = cc * (O1i - s * O1r);
    float T2r = s * O2i,              T2i = -s * O2r;
    float T3r = cc * (s * O3i - O3r), T3i = -cc * (O3i + s * O3r);
    zr[0] = E0r + T0r; zi[0] = E0i + T0i;
    zr[4] = E0r - T0r; zi[4] = E0i - T0i;
    zr[1] = E1r + T1r; zi[1] = E1i + T1i;
    zr[5] = E1r - T1r; zi[5] = E1i - T1i;
    zr[2] = E2r + T2r; zi[2] = E2i + T2i;
    zr[6] = E2r - T2r; zi[6] = E2i - T2i;
    zr[3] = E3r + T3r; zi[3] = E3i + T3i;
    zr[7] = E3r - T3r; zi[7] = E3i - T3i;
}

// rfft2 of an 8x8 real patch (x[r*8+c], contiguous). Output: half spectrum
// F[u][v], u=0..7, v=0..4 stored at index u*5+v.
__device__ __forceinline__ void rfft2_8x8(const float* __restrict__ x,
                                          float Fr[40], float Fi[40])
{
    // rows: rfft along last axis (keep v = 0..4)
#pragma unroll
    for (int r = 0; r < 8; r++) {
        float zr[8], zi[8];
#pragma unroll
        for (int c = 0; c < 8; c++) { zr[c] = x[r * 8 + c]; zi[c] = 0.f; }
        cfft8(zr, zi, 1.0f);
#pragma unroll
        for (int v = 0; v < 5; v++) { Fr[r * 5 + v] = zr[v]; Fi[r * 5 + v] = zi[v]; }
    }
    // columns: full complex fft along axis -2
#pragma unroll
    for (int v = 0; v < 5; v++) {
        float zr[8], zi[8];
#pragma unroll
        for (int u = 0; u < 8; u++) { zr[u] = Fr[u * 5 + v]; zi[u] = Fi[u * 5 + v]; }
        cfft8(zr, zi, 1.0f);
#pragma unroll
        for (int u = 0; u < 8; u++) { Fr[u * 5 + v] = zr[u]; Fi[u * 5 + v] = zi[u]; }
    }
}

// ---------------------------------------------------------------------------
// Kernel F: per patch (b, ph, pw): 1x1 convs (GEMM 256x64, k=64) + forward
// FFTs + filter + combine + inverse FFT; writes un-patched x to g_xmid.
// smem (floats):
//   [0,16384)      sWT  [64][256]  weights transposed (img | event)
//   [16384,24576)  sIn  [2][64][64] pixels
//   [24576,41216)  sMid [256][65]  GEMM results (padded rows)
//   [41216,46464)  sFilt[128][41]
//   sFFT [256][81] aliases [0,20736) after the GEMM phase.
// ---------------------------------------------------------------------------
__global__ void __launch_bounds__(256) kF(const float* __restrict__ img,
                                          const float* __restrict__ evt,
                                          const float* __restrict__ w_img,
                                          const float* __restrict__ w_evt,
                                          const float* __restrict__ filt)
{
    extern __shared__ float sm[];
    float* sWT   = sm;            // [64][256]
    float* sIn   = sm + 16384;    // [2][64][64]
    float* sMid  = sm + 24576;    // [256][65]
    float* sFilt = sm + 41216;    // [128][41]
    float* sFFT  = sm;            // [256][81], reuses sWT+sIn region

    const int tid = threadIdx.x;
    const int pw = blockIdx.x, ph = blockIdx.y, b = blockIdx.z;

    // load weights transposed: sWT[k][o] (o<128: img, o>=128: event)
    for (int i = tid; i < 64 * 128; i += 256) {
        int k = i >> 7, o = i & 127;
        sWT[k * 256 + o]       = w_img[o * 64 + k];
        sWT[k * 256 + 128 + o] = w_evt[o * 64 + k];
    }
    // filter [128][40] -> padded [128][41]
    for (int i = tid; i < 128 * 40; i += 256) {
        int o = i / 40, j = i - o * 40;
        sFilt[o * 41 + j] = filt[i];
    }
    // patch pixels: 64 channels x 64 px, float4 loads
    {
        const float4* img4 = reinterpret_cast<const float4*>(img);
        const float4* evt4 = reinterpret_cast<const float4*>(evt);
        for (int i = tid; i < 64 * 16; i += 256) {
            int c = i >> 4, q = i & 15;
            int r = q >> 1, h = q & 1;
            int g4 = (((b * 64 + c) * 256 + ph * 8 + r) * 256 + pw * 8) / 4 + h;
            float4 v0 = img4[g4];
            float4 v1 = evt4[g4];
            *reinterpret_cast<float4*>(&sIn[c * 64 + q * 4])        = v0;
            *reinterpret_cast<float4*>(&sIn[4096 + c * 64 + q * 4]) = v1;
        }
    }
    __syncthreads();

    // GEMM: rows 0..255 (channel slots) x cols 0..63 (pixels), k = 64
    {
        int rb = tid >> 3, cb = tid & 7;
        int r0 = rb * 8, c0 = cb * 8;
        const float* pin = sIn + ((r0 >= 128) ? 4096 : 0);
        float acc[64];
#pragma unroll
        for (int i = 0; i < 64; i++) acc[i] = 0.f;
#pragma unroll 4
        for (int k = 0; k < 64; k++) {
            float4 w0 = *reinterpret_cast<const float4*>(&sWT[k * 256 + r0]);
            float4 w1 = *reinterpret_cast<const float4*>(&sWT[k * 256 + r0 + 4]);
            float4 x0 = *reinterpret_cast<const float4*>(&pin[k * 64 + c0]);
            float4 x1 = *reinterpret_cast<const float4*>(&pin[k * 64 + c0 + 4]);
            float wv[8] = {w0.x, w0.y, w0.z, w0.w, w1.x, w1.y, w1.z, w1.w};
            float xv[8] = {x0.x, x0.y, x0.z, x0.w, x1.x, x1.y, x1.z, x1.w};
#pragma unroll
            for (int i = 0; i < 8; i++)
#pragma unroll
                for (int j = 0; j < 8; j++)
                    acc[i * 8 + j] = fmaf(wv[i], xv[j], acc[i * 8 + j]);
        }
#pragma unroll
        for (int i = 0; i < 8; i++)
#pragma unroll
            for (int j = 0; j < 8; j++)
                sMid[(r0 + i) * 65 + c0 + j] = acc[i * 8 + j];
    }
    __syncthreads();   // after this, sWT/sIn region is reusable as sFFT

    // forward FFTs: threads 0..127 -> event (with filter), 128..255 -> img
    {
        int o = tid & 127;
        bool isEvt = (tid < 128);
        const float* src = sMid + (isEvt ? (128 + o) : o) * 65;
        float Fr[40], Fi[40];
        rfft2_8x8(src, Fr, Fi);
        if (isEvt) {
#pragma unroll
            for (int j = 0; j < 40; j++) {
                float f = sFilt[o * 41 + j];
                Fr[j] *= f; Fi[j] *= f;
            }
        }
        float* dst = sFFT + (isEvt ? o : (128 + o)) * 81;
#pragma unroll
        for (int j = 0; j < 40; j++) { dst[j] = Fr[j]; dst[40 + j] = Fi[j]; }
    }
    __syncthreads();

    // combine + inverse (threads 0..127, one channel each)
    if (tid < 128) {
        int o = tid;
        const float* ev = sFFT + o * 81;
        const float* im = sFFT + (128 + o) * 81;
        float Xr[40], Xi[40];
#pragma unroll
        for (int j = 0; j < 40; j++) {
            float er = ev[j], ei = ev[40 + j];
            float ir = im[j] + 1.0f, ii = im[40 + j];
            Xr[j] = ir * er - ii * ei;
            Xi[j] = ir * ei + ii * er;
        }
        // inverse fft along columns (axis -2)
#pragma unroll
        for (int v = 0; v < 5; v++) {
            float zr[8], zi[8];
#pragma unroll
            for (int u = 0; u < 8; u++) { zr[u] = Xr[u * 5 + v]; zi[u] = Xi[u * 5 + v]; }
            cfft8(zr, zi, -1.0f);
#pragma unroll
            for (int u = 0; u < 8; u++) { Xr[u * 5 + v] = zr[u]; Xi[u * 5 + v] = zi[u]; }
        }
        // irfft along rows (hermitian extension; real part only), scale 1/64
        float* outp = g_xmid + (((size_t)(b * 128 + o) * 256 + ph * 8) * 256 + pw * 8);
        const float sc = 1.0f / 64.0f;
#pragma unroll
        for (int r = 0; r < 8; r++) {
            float zr[8], zi[8];
#pragma unroll
            for (int v = 0; v < 5; v++) { zr[v] = Xr[r * 5 + v]; zi[v] = Xi[r * 5 + v]; }
            zr[5] = Xr[r * 5 + 3]; zi[5] = -Xi[r * 5 + 3];
            zr[6] = Xr[r * 5 + 2]; zi[6] = -Xi[r * 5 + 2];
            zr[7] = Xr[r * 5 + 1]; zi[7] = -Xi[r * 5 + 1];
            cfft8(zr, zi, -1.0f);
            float4 o0 = {zr[0] * sc, zr[1] * sc, zr[2] * sc, zr[3] * sc};
            float4 o1 = {zr[4] * sc, zr[5] * sc, zr[6] * sc, zr[7] * sc};
            *reinterpret_cast<float4*>(&outp[r * 256])     = o0;
            *reinterpret_cast<float4*>(&outp[r * 256 + 4]) = o1;
        }
    }
}

// ---------------------------------------------------------------------------
// Kernel D: 16x16 output tile per block. Depthwise 3x3 (SAME, zero pad) on
// channels c and c+64, exact GELU gate, then 64x64 out 1x1 GEMM.
// smem (floats): sG[64][256]=16384 | sWoT[64][64]=4096 | sWdw[1152] | sHalo[2][18][20]=720
// ---------------------------------------------------------------------------
__global__ void __launch_bounds__(256) kD(const float* __restrict__ w_dw,
                                          const float* __restrict__ w_out,
                                          float* __restrict__ out)
{
    extern __shared__ float sm[];
    float* sG    = sm;           // [64][256]
    float* sWoT  = sm + 16384;   // [64][64] transposed: sWoT[k][o]
    float* sWdw  = sm + 20480;   // [128][9]
    float* sHalo = sm + 21632;   // [2][18][20]

    const int tid = threadIdx.x;
    const int bx = blockIdx.x, by = blockIdx.y, b = blockIdx.z;
    const int x0 = bx * 16, y0 = by * 16;

    for (int i = tid; i < 64 * 64; i += 256) {
        int k = i >> 6, o = i & 63;
        sWoT[k * 64 + o] = w_out[o * 64 + k];
    }
    for (int i = tid; i < 128 * 9; i += 256) sWdw[i] = w_dw[i];

    const int py = tid >> 4, px = tid & 15;
    const size_t cbase = (size_t)b * 128 * 65536;

    for (int c = 0; c < 64; c++) {
        __syncthreads();  // protect sHalo reuse (also covers sWdw on iter 0)
        for (int i = tid; i < 324; i += 256) {
            int y = i / 18, x = i - y * 18;
            int gy = y0 + y - 1, gx = x0 + x - 1;
            float v0 = 0.f, v1 = 0.f;
            if (gy >= 0 && gy < 256 && gx >= 0 && gx < 256) {
                size_t gi = cbase + (size_t)c * 65536 + (size_t)gy * 256 + gx;
                v0 = g_xmid[gi];
                v1 = g_xmid[gi + (size_t)64 * 65536];
            }
            sHalo[y * 20 + x]       = v0;
            sHalo[360 + y * 20 + x] = v1;
        }
        __syncthreads();
        float a = 0.f, bb = 0.f;
#pragma unroll
        for (int dy = 0; dy < 3; dy++)
#pragma unroll
            for (int dx = 0; dx < 3; dx++) {
                float w1 = sWdw[c * 9 + dy * 3 + dx];
                float w2 = sWdw[(c + 64) * 9 + dy * 3 + dx];
                a  = fmaf(sHalo[(py + dy) * 20 + px + dx],       w1, a);
                bb = fmaf(sHalo[360 + (py + dy) * 20 + px + dx], w2, bb);
            }
        float gl = 0.5f * a * (1.0f + erff(a * 0.70710678118654752f));
        sG[c * 256 + tid] = gl * bb;
    }
    __syncthreads();

    // out GEMM: 64 oc x 256 px, k = 64; per thread 8 oc x 8 px
    int ob = tid >> 5, pb = tid & 31;
    int oc0 = ob * 8, p0 = pb * 8;
    float acc[64];
#pragma unroll
    for (int i = 0; i < 64; i++) acc[i] = 0.f;
#pragma unroll 4
    for (int k = 0; k < 64; k++) {
        float4 w0 = *reinterpret_cast<const float4*>(&sWoT[k * 64 + oc0]);
        float4 w1 = *reinterpret_cast<const float4*>(&sWoT[k * 64 + oc0 + 4]);
        float4 g0 = *reinterpret_cast<const float4*>(&sG[k * 256 + p0]);
        float4 g1 = *reinterpret_cast<const float4*>(&sG[k * 256 + p0 + 4]);
        float wv[8] = {w0.x, w0.y, w0.z, w0.w, w1.x, w1.y, w1.z, w1.w};
        float gv[8] = {g0.x, g0.y, g0.z, g0.w, g1.x, g1.y, g1.z, g1.w};
#pragma unroll
        for (int i = 0; i < 8; i++)
#pragma unroll
            for (int j = 0; j < 8; j++)
                acc[i * 8 + j] = fmaf(wv[i], gv[j], acc[i * 8 + j]);
    }
    // write: each 8-px group is a half row of the 16x16 tile
    int wy = y0 + (p0 >> 4);
    int wx = x0 + (p0 & 15);
#pragma unroll
    for (int i = 0; i < 8; i++) {
        size_t ga = ((size_t)(b * 64 + oc0 + i) * 256 + wy) * 256 + wx;
        float4 q0 = {acc[i * 8 + 0], acc[i * 8 + 1], acc[i * 8 + 2], acc[i * 8 + 3]};
        float4 q1 = {acc[i * 8 + 4], acc[i * 8 + 5], acc[i * 8 + 6], acc[i * 8 + 7]};
        *reinterpret_cast<float4*>(&out[ga])     = q0;
        *reinterpret_cast<float4*>(&out[ga + 4]) = q1;
    }
}

// ---------------------------------------------------------------------------
extern "C" void kernel_launch(void* const* d_in, const int* in_sizes, int n_in,
                              void* d_out, int out_size)
{
    const float* img   = (const float*)d_in[0];
    const float* evt   = (const float*)d_in[1];
    const float* w_img = (const float*)d_in[2];
    const float* w_evt = (const float*)d_in[3];
    const float* w_dw  = (const float*)d_in[4];
    const float* filt  = (const float*)d_in[5];
    const float* w_out = (const float*)d_in[6];
    float* out = (float*)d_out;

    const int smemF = 46464 * 4;  // 185,856 B
    const int smemD = 22352 * 4;  //  89,408 B
    cudaFuncSetAttribute(kF, cudaFuncAttributeMaxDynamicSharedMemorySize, smemF);
    cudaFuncSetAttribute(kD, cudaFuncAttributeMaxDynamicSharedMemorySize, smemD);

    kF<<<dim3(32, 32, 4), 256, smemF>>>(img, evt, w_img, w_evt, filt);
    kD<<<dim3(16, 16, 4), 256, smemD>>>(w_dw, w_out, out);
}

// round 4
// speedup vs baseline: 1.3652x; 1.3642x over previous
#include <cuda_runtime.h>
#include <cstdint>
#include <cmath>

// scratch: mid tensor x [4,128,256,256] and gated tensor [4,64,256,256]
static __device__ float g_xmid[(size_t)4 * 128 * 256 * 256];
static __device__ float g_gate[(size_t)4 * 64 * 256 * 256];

// ---------------------------------------------------------------------------
// 8-point complex FFT. s = +1: forward (e^{-i}), s = -1: inverse (e^{+i}),
// NO scaling. Fully unrolled, register-resident.
// ---------------------------------------------------------------------------
__device__ __forceinline__ void cfft8(float zr[8], float zi[8], const float s)
{
    const float cc = 0.70710678118654752440f;
    float t0r = zr[0] + zr[4], t0i = zi[0] + zi[4];
    float t1r = zr[0] - zr[4], t1i = zi[0] - zi[4];
    float t2r = zr[2] + zr[6], t2i = zi[2] + zi[6];
    float t3r = zr[2] - zr[6], t3i = zi[2] - zi[6];
    float E0r = t0r + t2r, E0i = t0i + t2i;
    float E2r = t0r - t2r, E2i = t0i - t2i;
    float E1r = t1r + s * t3i, E1i = t1i - s * t3r;
    float E3r = t1r - s * t3i, E3i = t1i + s * t3r;
    float u0r = zr[1] + zr[5], u0i = zi[1] + zi[5];
    float u1r = zr[1] - zr[5], u1i = zi[1] - zi[5];
    float u2r = zr[3] + zr[7], u2i = zi[3] + zi[7];
    float u3r = zr[3] - zr[7], u3i = zi[3] - zi[7];
    float O0r = u0r + u2r, O0i = u0i + u2i;
    float O2r = u0r - u2r, O2i = u0i - u2i;
    float O1r = u1r + s * u3i, O1i = u1i - s * u3r;
    float O3r = u1r - s * u3i, O3i = u1i + s * u3r;
    float T0r = O0r, T0i = O0i;
    float T1r = cc * (O1r + s * O1i), T1i = cc * (O1i - s * O1r);
    float T2r = s * O2i,              T2i = -s * O2r;
    float T3r = cc * (s * O3i - O3r), T3i = -cc * (O3i + s * O3r);
    zr[0] = E0r + T0r; zi[0] = E0i + T0i;
    zr[4] = E0r - T0r; zi[4] = E0i - T0i;
    zr[1] = E1r + T1r; zi[1] = E1i + T1i;
    zr[5] = E1r - T1r; zi[5] = E1i - T1i;
    zr[2] = E2r + T2r; zi[2] = E2i + T2i;
    zr[6] = E2r - T2r; zi[6] = E2i - T2i;
    zr[3] = E3r + T3r; zi[3] = E3i + T3i;
    zr[7] = E3r - T3r; zi[7] = E3i - T3i;
}

// ---------------------------------------------------------------------------
// Kernel F (512 threads): per patch (b,ph,pw):
//   1) 1x1 conv GEMM 256x64 (k=64) -> sMid
//   2) per channel o (threads 0..127): PACKED complex FFT of img + i*event,
//      hermitian split, filter, combine X=(I+1)(f*E), inverse FFT, store.
// smem (floats): sWT[64][256]=16384 | sIn[2][64][64]=8192 | sMid[256][65]=16640
// phase-2 alias: sZ[128][129] (= 16512) over sWT/sIn region (dead post-GEMM).
// total = 41216 floats = 164,864 B
// ---------------------------------------------------------------------------
__global__ void __launch_bounds__(512) kF(const float* __restrict__ img,
                                          const float* __restrict__ evt,
                                          const float* __restrict__ w_img,
                                          const float* __restrict__ w_evt,
                                          const float* __restrict__ filt)
{
    extern __shared__ float sm[];
    float* sWT  = sm;            // [64][256]
    float* sIn  = sm + 16384;    // [2][64][64]
    float* sMid = sm + 24576;    // [256][65]

    const int tid = threadIdx.x;
    const int pw = blockIdx.x, ph = blockIdx.y, b = blockIdx.z;

    // weights transposed: sWT[k][o] (o<128: img, o>=128: event)
    for (int i = tid; i < 64 * 128; i += 512) {
        int k = i >> 7, o = i & 127;
        sWT[k * 256 + o]       = w_img[o * 64 + k];
        sWT[k * 256 + 128 + o] = w_evt[o * 64 + k];
    }
    // patch pixels
    {
        const float4* img4 = reinterpret_cast<const float4*>(img);
        const float4* evt4 = reinterpret_cast<const float4*>(evt);
        for (int i = tid; i < 64 * 16; i += 512) {
            int c = i >> 4, q = i & 15;
            int r = q >> 1, h = q & 1;
            int g4 = (((b * 64 + c) * 256 + ph * 8 + r) * 256 + pw * 8) / 4 + h;
            *reinterpret_cast<float4*>(&sIn[c * 64 + q * 4])        = img4[g4];
            *reinterpret_cast<float4*>(&sIn[4096 + c * 64 + q * 4]) = evt4[g4];
        }
    }
    __syncthreads();

    // GEMM: 256 rows (channels) x 64 cols (pixels), k=64; thread tile 8x4
    {
        int rb = tid >> 4, cb = tid & 15;
        int r0 = rb * 8, c0 = cb * 4;
        const float* pin = sIn + ((r0 >= 128) ? 4096 : 0);
        float acc[32];
#pragma unroll
        for (int i = 0; i < 32; i++) acc[i] = 0.f;
#pragma unroll 4
        for (int k = 0; k < 64; k++) {
            float4 w0 = *reinterpret_cast<const float4*>(&sWT[k * 256 + r0]);
            float4 w1 = *reinterpret_cast<const float4*>(&sWT[k * 256 + r0 + 4]);
            float4 x0 = *reinterpret_cast<const float4*>(&pin[k * 64 + c0]);
            float wv[8] = {w0.x, w0.y, w0.z, w0.w, w1.x, w1.y, w1.z, w1.w};
            float xv[4] = {x0.x, x0.y, x0.z, x0.w};
#pragma unroll
            for (int i = 0; i < 8; i++)
#pragma unroll
                for (int j = 0; j < 4; j++)
                    acc[i * 4 + j] = fmaf(wv[i], xv[j], acc[i * 4 + j]);
        }
#pragma unroll
        for (int i = 0; i < 8; i++)
#pragma unroll
            for (int j = 0; j < 4; j++)
                sMid[(r0 + i) * 65 + c0 + j] = acc[i * 4 + j];
    }
    __syncthreads();   // sWT/sIn region now dead -> reusable as sZ

    // phase 2: packed FFT pipeline, one channel per thread (tid < 128),
    // all staging is thread-private (sZ row o) => no further syncs needed.
    if (tid < 128) {
        const int o = tid;
        float* sZ = sm + o * 129;              // 64 complex, interleaved
        const float* mi = sMid + o * 65;        // img_ patch (row-major 8x8)
        const float* me = sMid + (128 + o) * 65; // event_ patch

        // stage A: row FFTs of z = img + i*event
#pragma unroll
        for (int r = 0; r < 8; r++) {
            float zr[8], zi[8];
#pragma unroll
            for (int c = 0; c < 8; c++) { zr[c] = mi[r * 8 + c]; zi[c] = me[r * 8 + c]; }
            cfft8(zr, zi, 1.0f);
#pragma unroll
            for (int c = 0; c < 8; c++) {
                sZ[(r * 8 + c) * 2]     = zr[c];
                sZ[(r * 8 + c) * 2 + 1] = zi[c];
            }
        }

        // stage B: per column-pair (v, 8-v): column FFTs, hermitian split,
        // filter, combine, inverse column FFT; write Xc back into column v.
        const float* fo = filt + o * 40;
        const int vv[5] = {0, 4, 1, 2, 3};
        const int mm[5] = {0, 4, 7, 6, 5};
#pragma unroll
        for (int pidx = 0; pidx < 5; pidx++) {
            const int v = vv[pidx], m = mm[pidx];
            float Pr[8], Pi[8], Qr[8], Qi[8];
#pragma unroll
            for (int u = 0; u < 8; u++) {
                Pr[u] = sZ[(u * 8 + v) * 2];
                Pi[u] = sZ[(u * 8 + v) * 2 + 1];
            }
            cfft8(Pr, Pi, 1.0f);
            if (m == v) {
#pragma unroll
                for (int u = 0; u < 8; u++) { Qr[u] = Pr[u]; Qi[u] = Pi[u]; }
            } else {
#pragma unroll
                for (int u = 0; u < 8; u++) {
                    Qr[u] = sZ[(u * 8 + m) * 2];
                    Qi[u] = sZ[(u * 8 + m) * 2 + 1];
                }
                cfft8(Qr, Qi, 1.0f);
            }
            // split: I = FFT(img), E = FFT(event); combine X=(I+1)*(f*E)
            float Xr[8], Xi[8];
#pragma unroll
            for (int u = 0; u < 8; u++) {
                int n = (8 - u) & 7;
                float pr = Pr[u], pi = Pi[u], qr = Qr[n], qi = Qi[n];
                float Ir = 0.5f * (pr + qr), Ii = 0.5f * (pi - qi);
                float f  = fo[u * 5 + v];
                float Er = 0.5f * f * (pi + qi), Ei = 0.5f * f * (qr - pr);
                float ar = Ir + 1.0f;
                Xr[u] = ar * Er - Ii * Ei;
                Xi[u] = ar * Ei + Ii * Er;
            }
            cfft8(Xr, Xi, -1.0f);   // inverse along u
#pragma unroll
            for (int r = 0; r < 8; r++) {
                sZ[(r * 8 + v) * 2]     = Xr[r];
                sZ[(r * 8 + v) * 2 + 1] = Xi[r];
            }
        }

        // stage C: row inverse (hermitian extension over v), scale, store
        float* outp = g_xmid + (((size_t)(b * 128 + o) * 256 + ph * 8) * 256 + pw * 8);
        const float sc = 1.0f / 64.0f;
#pragma unroll
        for (int r = 0; r < 8; r++) {
            float zr[8], zi[8];
#pragma unroll
            for (int v = 0; v < 5; v++) {
                zr[v] = sZ[(r * 8 + v) * 2];
                zi[v] = sZ[(r * 8 + v) * 2 + 1];
            }
            zr[5] = zr[3]; zi[5] = -zi[3];
            zr[6] = zr[2]; zi[6] = -zi[2];
            zr[7] = zr[1]; zi[7] = -zi[1];
            cfft8(zr, zi, -1.0f);
            float4 o0 = {zr[0] * sc, zr[1] * sc, zr[2] * sc, zr[3] * sc};
            float4 o1 = {zr[4] * sc, zr[5] * sc, zr[6] * sc, zr[7] * sc};
            *reinterpret_cast<float4*>(&outp[r * 256])     = o0;
            *reinterpret_cast<float4*>(&outp[r * 256 + 4]) = o1;
        }
    }
}

// ---------------------------------------------------------------------------
// Kernel DW: depthwise 3x3 (SAME) on channel pair (c, c+64), exact GELU gate.
// Block = 64x16 pixel tile of one (b, c). One halo load, one sync.
// ---------------------------------------------------------------------------
__global__ void __launch_bounds__(256) kDW(const float* __restrict__ w_dw)
{
    __shared__ float sH[2 * 18 * 68];   // [2][18][68] padded rows

    const int tid = threadIdx.x;
    const int b = blockIdx.z >> 6, c = blockIdx.z & 63;
    const int x0 = blockIdx.x * 64, y0 = blockIdx.y * 16;

    float w1[9], w2[9];
#pragma unroll
    for (int j = 0; j < 9; j++) {
        w1[j] = w_dw[c * 9 + j];
        w2[j] = w_dw[(c + 64) * 9 + j];
    }

    const float* src0 = g_xmid + (size_t)(b * 128 + c) * 65536;
    const float* src1 = src0 + (size_t)64 * 65536;

    for (int i = tid; i < 18 * 66; i += 256) {
        int y = i / 66, x = i - y * 66;
        int gy = y0 + y - 1, gx = x0 + x - 1;
        float v0 = 0.f, v1 = 0.f;
        if (gy >= 0 && gy < 256 && gx >= 0 && gx < 256) {
            size_t gi = (size_t)gy * 256 + gx;
            v0 = src0[gi];
            v1 = src1[gi];
        }
        sH[y * 68 + x]        = v0;
        sH[1224 + y * 68 + x] = v1;
    }
    __syncthreads();

    const int px = tid & 63, ty = tid >> 6;   // ty 0..3 -> 4 rows each
    float* dst = g_gate + (size_t)(b * 64 + c) * 65536;
#pragma unroll
    for (int yy = 0; yy < 4; yy++) {
        int py = ty * 4 + yy;
        float a = 0.f, bb = 0.f;
#pragma unroll
        for (int dy = 0; dy < 3; dy++)
#pragma unroll
            for (int dx = 0; dx < 3; dx++) {
                a  = fmaf(sH[(py + dy) * 68 + px + dx],        w1[dy * 3 + dx], a);
                bb = fmaf(sH[1224 + (py + dy) * 68 + px + dx], w2[dy * 3 + dx], bb);
            }
        float gl = 0.5f * a * (1.0f + erff(a * 0.70710678118654752f));
        dst[(size_t)(y0 + py) * 256 + x0 + px] = gl * bb;
    }
}

// ---------------------------------------------------------------------------
// Kernel Out: 1x1 projection. Block = one image row (256 px), all 64 k.
// GEMM 64oc x 256px x 64k, thread tile 8x8.
// smem: sG[64][256]=16384 | sWoT[64][64]=4096  -> 81,920 B (2 blocks/SM)
// ---------------------------------------------------------------------------
__global__ void __launch_bounds__(256) kOut(const float* __restrict__ w_out,
                                            float* __restrict__ out)
{
    extern __shared__ float sm[];
    float* sG   = sm;          // [64][256]
    float* sWoT = sm + 16384;  // [64][64] transposed: sWoT[k][o]

    const int tid = threadIdx.x;
    const int y = blockIdx.x, b = blockIdx.y;

    for (int i = tid; i < 64 * 64; i += 256) {
        int k = i >> 6, o = i & 63;
        sWoT[k * 64 + o] = w_out[o * 64 + k];
    }
    for (int i = tid; i < 64 * 256; i += 256) {
        int k = i >> 8, p = i & 255;
        sG[i] = g_gate[(size_t)(b * 64 + k) * 65536 + (size_t)y * 256 + p];
    }
    __syncthreads();

    int ob = tid >> 5, pb = tid & 31;
    int oc0 = ob * 8, p0 = pb * 8;
    float acc[64];
#pragma unroll
    for (int i = 0; i < 64; i++) acc[i] = 0.f;
#pragma unroll 4
    for (int k = 0; k < 64; k++) {
        float4 w0 = *reinterpret_cast<const float4*>(&sWoT[k * 64 + oc0]);
        float4 w1 = *reinterpret_cast<const float4*>(&sWoT[k * 64 + oc0 + 4]);
        float4 g0 = *reinterpret_cast<const float4*>(&sG[k * 256 + p0]);
        float4 g1 = *reinterpret_cast<const float4*>(&sG[k * 256 + p0 + 4]);
        float wv[8] = {w0.x, w0.y, w0.z, w0.w, w1.x, w1.y, w1.z, w1.w};
        float gv[8] = {g0.x, g0.y, g0.z, g0.w, g1.x, g1.y, g1.z, g1.w};
#pragma unroll
        for (int i = 0; i < 8; i++)
#pragma unroll
            for (int j = 0; j < 8; j++)
                acc[i * 8 + j] = fmaf(wv[i], gv[j], acc[i * 8 + j]);
    }
#pragma unroll
    for (int i = 0; i < 8; i++) {
        size_t ga = ((size_t)(b * 64 + oc0 + i) * 256 + y) * 256 + p0;
        float4 q0 = {acc[i * 8 + 0], acc[i * 8 + 1], acc[i * 8 + 2], acc[i * 8 + 3]};
        float4 q1 = {acc[i * 8 + 4], acc[i * 8 + 5], acc[i * 8 + 6], acc[i * 8 + 7]};
        *reinterpret_cast<float4*>(&out[ga])     = q0;
        *reinterpret_cast<float4*>(&out[ga + 4]) = q1;
    }
}

// ---------------------------------------------------------------------------
extern "C" void kernel_launch(void* const* d_in, const int* in_sizes, int n_in,
                              void* d_out, int out_size)
{
    const float* img   = (const float*)d_in[0];
    const float* evt   = (const float*)d_in[1];
    const float* w_img = (const float*)d_in[2];
    const float* w_evt = (const float*)d_in[3];
    const float* w_dw  = (const float*)d_in[4];
    const float* filt  = (const float*)d_in[5];
    const float* w_out = (const float*)d_in[6];
    float* out = (float*)d_out;

    const int smemF = 41216 * 4;   // 164,864 B
    const int smemO = 20480 * 4;   //  81,920 B
    cudaFuncSetAttribute(kF,   cudaFuncAttributeMaxDynamicSharedMemorySize, smemF);
    cudaFuncSetAttribute(kOut, cudaFuncAttributeMaxDynamicSharedMemorySize, smemO);

    kF<<<dim3(32, 32, 4), 512, smemF>>>(img, evt, w_img, w_evt, filt);
    kDW<<<dim3(4, 16, 256), 256>>>(w_dw);
    kOut<<<dim3(256, 4), 256, smemO>>>(w_out, out);
}

// round 5
// speedup vs baseline: 1.4905x; 1.0918x over previous
#include <cuda_runtime.h>
#include <cstdint>
#include <cmath>

// scratch: mid tensor x [4,128,256,256] and gated tensor [4,64,256,256]
static __device__ float g_xmid[(size_t)4 * 128 * 256 * 256];
static __device__ float g_gate[(size_t)4 * 64 * 256 * 256];

// ---------------------------------------------------------------------------
// f32x2 packed helpers (Blackwell FFMA2 path — only reachable via PTX)
// ---------------------------------------------------------------------------
__device__ __forceinline__ unsigned long long pack2(float lo, float hi)
{
    unsigned long long r;
    asm("mov.b64 %0, {%1, %2};" : "=l"(r) : "f"(lo), "f"(hi));
    return r;
}
__device__ __forceinline__ void unpack2(unsigned long long v, float& lo, float& hi)
{
    asm("mov.b64 {%0, %1}, %2;" : "=f"(lo), "=f"(hi) : "l"(v));
}
__device__ __forceinline__ unsigned long long fma2(unsigned long long a,
                                                   unsigned long long b,
                                                   unsigned long long c)
{
    unsigned long long d;
    asm("fma.rn.f32x2 %0, %1, %2, %3;" : "=l"(d) : "l"(a), "l"(b), "l"(c));
    return d;
}

// ---------------------------------------------------------------------------
// 8-point complex FFT. s = +1: forward (e^{-i}), s = -1: inverse (e^{+i}),
// NO scaling. Fully unrolled, register-resident.
// ---------------------------------------------------------------------------
__device__ __forceinline__ void cfft8(float zr[8], float zi[8], const float s)
{
    const float cc = 0.70710678118654752440f;
    float t0r = zr[0] + zr[4], t0i = zi[0] + zi[4];
    float t1r = zr[0] - zr[4], t1i = zi[0] - zi[4];
    float t2r = zr[2] + zr[6], t2i = zi[2] + zi[6];
    float t3r = zr[2] - zr[6], t3i = zi[2] - zi[6];
    float E0r = t0r + t2r, E0i = t0i + t2i;
    float E2r = t0r - t2r, E2i = t0i - t2i;
    float E1r = t1r + s * t3i, E1i = t1i - s * t3r;
    float E3r = t1r - s * t3i, E3i = t1i + s * t3r;
    float u0r = zr[1] + zr[5], u0i = zi[1] + zi[5];
    float u1r = zr[1] - zr[5], u1i = zi[1] - zi[5];
    float u2r = zr[3] + zr[7], u2i = zi[3] + zi[7];
    float u3r = zr[3] - zr[7], u3i = zi[3] - zi[7];
    float O0r = u0r + u2r, O0i = u0i + u2i;
    float O2r = u0r - u2r, O2i = u0i - u2i;
    float O1r = u1r + s * u3i, O1i = u1i - s * u3r;
    float O3r = u1r - s * u3i, O3i = u1i + s * u3r;
    float T0r = O0r, T0i = O0i;
    float T1r = cc * (O1r + s * O1i), T1i = cc * (O1i - s * O1r);
    float T2r = s * O2i,              T2i = -s * O2r;
    float T3r = cc * (s * O3i - O3r), T3i = -cc * (O3i + s * O3r);
    zr[0] = E0r + T0r; zi[0] = E0i + T0i;
    zr[4] = E0r - T0r; zi[4] = E0i - T0i;
    zr[1] = E1r + T1r; zi[1] = E1i + T1i;
    zr[5] = E1r - T1r; zi[5] = E1i - T1i;
    zr[2] = E2r + T2r; zi[2] = E2i + T2i;
    zr[6] = E2r - T2r; zi[6] = E2i - T2i;
    zr[3] = E3r + T3r; zi[3] = E3i + T3i;
    zr[7] = E3r - T3r; zi[7] = E3i - T3i;
}

// ---------------------------------------------------------------------------
// Kernel F (256 threads, 2 blocks/SM): per patch (b,ph,pw):
//   1) 1x1 conv GEMM 256x64 (k=64), f32x2 FMAs, acc in registers
//   2) write acc -> sMid which ALIASES the dead sWT/sIn region
//   3) per channel o (threads 0..127): packed complex FFT of img + i*event,
//      hermitian split, filter, combine X=(I+1)(f*E), inverse FFT, store.
//      Z buffer reuses sMid rows o (real) and 128+o (imag) IN PLACE.
// smem: max(sWT[64][256] + sIn[2][64][64], sMid[256][65]) = 24576 floats = 98304 B
// ---------------------------------------------------------------------------
__global__ void __launch_bounds__(256, 2) kF(const float* __restrict__ img,
                                             const float* __restrict__ evt,
                                             const float* __restrict__ w_img,
                                             const float* __restrict__ w_evt,
                                             const float* __restrict__ filt)
{
    extern __shared__ float sm[];
    float* sWT  = sm;            // [64][256]  (phase 1)
    float* sIn  = sm + 16384;    // [2][64][64] (phase 1)
    float* sMid = sm;            // [256][65]  (phase 2, aliases sWT/sIn)

    const int tid = threadIdx.x;
    const int pw = blockIdx.x, ph = blockIdx.y, b = blockIdx.z;

    // weights transposed: sWT[k][o] (o<128: img, o>=128: event)
    for (int i = tid; i < 64 * 128; i += 256) {
        int k = i >> 7, o = i & 127;
        sWT[k * 256 + o]       = w_img[o * 64 + k];
        sWT[k * 256 + 128 + o] = w_evt[o * 64 + k];
    }
    // patch pixels
    {
        const float4* img4 = reinterpret_cast<const float4*>(img);
        const float4* evt4 = reinterpret_cast<const float4*>(evt);
        for (int i = tid; i < 64 * 16; i += 256) {
            int c = i >> 4, q = i & 15;
            int r = q >> 1, h = q & 1;
            int g4 = (((b * 64 + c) * 256 + ph * 8 + r) * 256 + pw * 8) / 4 + h;
            *reinterpret_cast<float4*>(&sIn[c * 64 + q * 4])        = img4[g4];
            *reinterpret_cast<float4*>(&sIn[4096 + c * 64 + q * 4]) = evt4[g4];
        }
    }
    __syncthreads();

    // GEMM: 256 rows (channel slots) x 64 cols (pixels), k=64; 8x8 per thread,
    // f32x2 packed: 32 FFMA2 per k per thread.
    unsigned long long acc[32];
#pragma unroll
    for (int i = 0; i < 32; i++) acc[i] = 0ULL;
    {
        const int rb = tid >> 3, cb = tid & 7;
        const int r0 = rb * 8, c0 = cb * 8;
        const float* pin = sIn + ((r0 >= 128) ? 4096 : 0);
#pragma unroll 8
        for (int k = 0; k < 64; k++) {
            float4 w0 = *reinterpret_cast<const float4*>(&sWT[k * 256 + r0]);
            float4 w1 = *reinterpret_cast<const float4*>(&sWT[k * 256 + r0 + 4]);
            ulonglong2 xa = *reinterpret_cast<const ulonglong2*>(&pin[k * 64 + c0]);
            ulonglong2 xb = *reinterpret_cast<const ulonglong2*>(&pin[k * 64 + c0 + 4]);
            unsigned long long xv[4] = {xa.x, xa.y, xb.x, xb.y};
            float wf[8] = {w0.x, w0.y, w0.z, w0.w, w1.x, w1.y, w1.z, w1.w};
#pragma unroll
            for (int i = 0; i < 8; i++) {
                unsigned long long wp = pack2(wf[i], wf[i]);
#pragma unroll
                for (int j = 0; j < 4; j++)
                    acc[i * 4 + j] = fma2(wp, xv[j], acc[i * 4 + j]);
            }
        }
    }
    __syncthreads();   // sWT/sIn now dead -> region becomes sMid

    // spill acc -> sMid [256][65]
    {
        const int rb = tid >> 3, cb = tid & 7;
        const int r0 = rb * 8, c0 = cb * 8;
#pragma unroll
        for (int i = 0; i < 8; i++)
#pragma unroll
            for (int j = 0; j < 4; j++) {
                float lo, hi;
                unpack2(acc[i * 4 + j], lo, hi);
                sMid[(r0 + i) * 65 + c0 + 2 * j]     = lo;
                sMid[(r0 + i) * 65 + c0 + 2 * j + 1] = hi;
            }
    }
    __syncthreads();

    // phase 2: packed FFT pipeline, one channel per thread (tid < 128).
    // Z lives IN PLACE: Zr -> sMid row o, Zi -> sMid row 128+o.
    if (tid < 128) {
        const int o = tid;
        float* Zr = sMid + o * 65;
        float* Zi = sMid + (128 + o) * 65;

        // stage A: row FFTs of z = img + i*event (reads rows, writes back in place)
#pragma unroll
        for (int r = 0; r < 8; r++) {
            float zr[8], zi[8];
#pragma unroll
            for (int c = 0; c < 8; c++) { zr[c] = Zr[r * 8 + c]; zi[c] = Zi[r * 8 + c]; }
            cfft8(zr, zi, 1.0f);
#pragma unroll
            for (int c = 0; c < 8; c++) { Zr[r * 8 + c] = zr[c]; Zi[r * 8 + c] = zi[c]; }
        }

        // stage B: per column pair (v, 8-v): column FFTs, hermitian split,
        // filter, combine X=(I+1)(f*E), inverse column FFT, write into col v.
        const float* fo = filt + o * 40;
        const int vv[5] = {0, 4, 1, 2, 3};
        const int mm[5] = {0, 4, 7, 6, 5};
#pragma unroll
        for (int pidx = 0; pidx < 5; pidx++) {
            const int v = vv[pidx], m = mm[pidx];
            float Pr[8], Pi[8], Qr[8], Qi[8];
#pragma unroll
            for (int u = 0; u < 8; u++) { Pr[u] = Zr[u * 8 + v]; Pi[u] = Zi[u * 8 + v]; }
            cfft8(Pr, Pi, 1.0f);
            if (m == v) {
#pragma unroll
                for (int u = 0; u < 8; u++) { Qr[u] = Pr[u]; Qi[u] = Pi[u]; }
            } else {
#pragma unroll
                for (int u = 0; u < 8; u++) { Qr[u] = Zr[u * 8 + m]; Qi[u] = Zi[u * 8 + m]; }
                cfft8(Qr, Qi, 1.0f);
            }
            float Xr[8], Xi[8];
#pragma unroll
            for (int u = 0; u < 8; u++) {
                int n = (8 - u) & 7;
                float pr = Pr[u], pi = Pi[u], qr = Qr[n], qi = Qi[n];
                float Ir = 0.5f * (pr + qr), Ii = 0.5f * (pi - qi);
                float f  = fo[u * 5 + v];
                float Er = 0.5f * f * (pi + qi), Ei = 0.5f * f * (qr - pr);
                float ar = Ir + 1.0f;
                Xr[u] = ar * Er - Ii * Ei;
                Xi[u] = ar * Ei + Ii * Er;
            }
            cfft8(Xr, Xi, -1.0f);
#pragma unroll
            for (int r = 0; r < 8; r++) { Zr[r * 8 + v] = Xr[r]; Zi[r * 8 + v] = Xi[r]; }
        }

        // stage C: row inverse (hermitian extension over v), scale, store
        float* outp = g_xmid + (((size_t)(b * 128 + o) * 256 + ph * 8) * 256 + pw * 8);
        const float sc = 1.0f / 64.0f;
#pragma unroll
        for (int r = 0; r < 8; r++) {
            float zr[8], zi[8];
#pragma unroll
            for (int v = 0; v < 5; v++) { zr[v] = Zr[r * 8 + v]; zi[v] = Zi[r * 8 + v]; }
            zr[5] = zr[3]; zi[5] = -zi[3];
            zr[6] = zr[2]; zi[6] = -zi[2];
            zr[7] = zr[1]; zi[7] = -zi[1];
            cfft8(zr, zi, -1.0f);
            float4 o0 = {zr[0] * sc, zr[1] * sc, zr[2] * sc, zr[3] * sc};
            float4 o1 = {zr[4] * sc, zr[5] * sc, zr[6] * sc, zr[7] * sc};
            *reinterpret_cast<float4*>(&outp[r * 256])     = o0;
            *reinterpret_cast<float4*>(&outp[r * 256 + 4]) = o1;
        }
    }
}

// ---------------------------------------------------------------------------
// Kernel DW: depthwise 3x3 (SAME) on channel pair (c, c+64), exact GELU gate.
// Block = 64x16 pixel tile of one (b, c). One halo load, one sync.
// ---------------------------------------------------------------------------
__global__ void __launch_bounds__(256) kDW(const float* __restrict__ w_dw)
{
    __shared__ float sH[2 * 18 * 68];   // [2][18][68] padded rows

    const int tid = threadIdx.x;
    const int b = blockIdx.z >> 6, c = blockIdx.z & 63;
    const int x0 = blockIdx.x * 64, y0 = blockIdx.y * 16;

    float w1[9], w2[9];
#pragma unroll
    for (int j = 0; j < 9; j++) {
        w1[j] = w_dw[c * 9 + j];
        w2[j] = w_dw[(c + 64) * 9 + j];
    }

    const float* src0 = g_xmid + (size_t)(b * 128 + c) * 65536;
    const float* src1 = src0 + (size_t)64 * 65536;

    for (int i = tid; i < 18 * 66; i += 256) {
        int y = i / 66, x = i - y * 66;
        int gy = y0 + y - 1, gx = x0 + x - 1;
        float v0 = 0.f, v1 = 0.f;
        if (gy >= 0 && gy < 256 && gx >= 0 && gx < 256) {
            size_t gi = (size_t)gy * 256 + gx;
            v0 = src0[gi];
            v1 = src1[gi];
        }
        sH[y * 68 + x]        = v0;
        sH[1224 + y * 68 + x] = v1;
    }
    __syncthreads();

    const int px = tid & 63, ty = tid >> 6;   // ty 0..3 -> 4 rows each
    float* dst = g_gate + (size_t)(b * 64 + c) * 65536;
#pragma unroll
    for (int yy = 0; yy < 4; yy++) {
        int py = ty * 4 + yy;
        float a = 0.f, bb = 0.f;
#pragma unroll
        for (int dy = 0; dy < 3; dy++)
#pragma unroll
            for (int dx = 0; dx < 3; dx++) {
                a  = fmaf(sH[(py + dy) * 68 + px + dx],        w1[dy * 3 + dx], a);
                bb = fmaf(sH[1224 + (py + dy) * 68 + px + dx], w2[dy * 3 + dx], bb);
            }
        float gl = 0.5f * a * (1.0f + erff(a * 0.70710678118654752f));
        dst[(size_t)(y0 + py) * 256 + x0 + px] = gl * bb;
    }
}

// ---------------------------------------------------------------------------
// Kernel Out: 1x1 projection. Block = one image row (256 px), all 64 k.
// GEMM 64oc x 256px x 64k, thread tile 8x8, f32x2 FMAs.
// smem: sG[64][256]=16384 | sWoT[64][64]=4096  -> 81,920 B (2 blocks/SM)
// ---------------------------------------------------------------------------
__global__ void __launch_bounds__(256, 2) kOut(const float* __restrict__ w_out,
                                               float* __restrict__ out)
{
    extern __shared__ float sm[];
    float* sG   = sm;          // [64][256]
    float* sWoT = sm + 16384;  // [64][64] transposed: sWoT[k][o]

    const int tid = threadIdx.x;
    const int y = blockIdx.x, b = blockIdx.y;

    for (int i = tid; i < 64 * 64; i += 256) {
        int k = i >> 6, o = i & 63;
        sWoT[k * 64 + o] = w_out[o * 64 + k];
    }
    for (int i = tid; i < 64 * 256; i += 256) {
        int k = i >> 8, p = i & 255;
        sG[i] = g_gate[(size_t)(b * 64 + k) * 65536 + (size_t)y * 256 + p];
    }
    __syncthreads();

    const int ob = tid >> 5, pb = tid & 31;
    const int oc0 = ob * 8, p0 = pb * 8;
    unsigned long long acc[32];
#pragma unroll
    for (int i = 0; i < 32; i++) acc[i] = 0ULL;
#pragma unroll 8
    for (int k = 0; k < 64; k++) {
        float4 w0 = *reinterpret_cast<const float4*>(&sWoT[k * 64 + oc0]);
        float4 w1 = *reinterpret_cast<const float4*>(&sWoT[k * 64 + oc0 + 4]);
        ulonglong2 ga = *reinterpret_cast<const ulonglong2*>(&sG[k * 256 + p0]);
        ulonglong2 gb = *reinterpret_cast<const ulonglong2*>(&sG[k * 256 + p0 + 4]);
        unsigned long long gv[4] = {ga.x, ga.y, gb.x, gb.y};
        float wf[8] = {w0.x, w0.y, w0.z, w0.w, w1.x, w1.y, w1.z, w1.w};
#pragma unroll
        for (int i = 0; i < 8; i++) {
            unsigned long long wp = pack2(wf[i], wf[i]);
#pragma unroll
            for (int j = 0; j < 4; j++)
                acc[i * 4 + j] = fma2(wp, gv[j], acc[i * 4 + j]);
        }
    }
#pragma unroll
    for (int i = 0; i < 8; i++) {
        float v[8];
#pragma unroll
        for (int j = 0; j < 4; j++) unpack2(acc[i * 4 + j], v[2 * j], v[2 * j + 1]);
        size_t ga = ((size_t)(b * 64 + oc0 + i) * 256 + y) * 256 + p0;
        float4 q0 = {v[0], v[1], v[2], v[3]};
        float4 q1 = {v[4], v[5], v[6], v[7]};
        *reinterpret_cast<float4*>(&out[ga])     = q0;
        *reinterpret_cast<float4*>(&out[ga + 4]) = q1;
    }
}

// ---------------------------------------------------------------------------
extern "C" void kernel_launch(void* const* d_in, const int* in_sizes, int n_in,
                              void* d_out, int out_size)
{
    const float* img   = (const float*)d_in[0];
    const float* evt   = (const float*)d_in[1];
    const float* w_img = (const float*)d_in[2];
    const float* w_evt = (const float*)d_in[3];
    const float* w_dw  = (const float*)d_in[4];
    const float* filt  = (const float*)d_in[5];
    const float* w_out = (const float*)d_in[6];
    float* out = (float*)d_out;

    const int smemF = 24576 * 4;   // 98,304 B  -> 2 blocks/SM
    const int smemO = 20480 * 4;   // 81,920 B  -> 2 blocks/SM
    cudaFuncSetAttribute(kF,   cudaFuncAttributeMaxDynamicSharedMemorySize, smemF);
    cudaFuncSetAttribute(kOut, cudaFuncAttributeMaxDynamicSharedMemorySize, smemO);

    kF<<<dim3(32, 32, 4), 256, smemF>>>(img, evt, w_img, w_evt, filt);
    kDW<<<dim3(4, 16, 256), 256>>>(w_dw);
    kOut<<<dim3(256, 4), 256, smemO>>>(w_out, out);
}

// round 6
// speedup vs baseline: 1.5519x; 1.0412x over previous
#include <cuda_runtime.h>
#include <cuda_fp16.h>
#include <cstdint>
#include <cmath>

// scratch
static __device__ __align__(16) __half g_mid_i[(size_t)4 * 128 * 256 * 256]; // img_  fp16
static __device__ __align__(16) __half g_mid_e[(size_t)4 * 128 * 256 * 256]; // event_ fp16
static __device__ float g_xmid[(size_t)4 * 128 * 256 * 256];                 // post-FFT x
static __device__ float g_gate[(size_t)4 * 64 * 256 * 256];                  // gated

// ---------------------------------------------------------------------------
// f32x2 packed helpers (Blackwell FFMA2 path — only reachable via PTX)
// ---------------------------------------------------------------------------
__device__ __forceinline__ unsigned long long pack2(float lo, float hi)
{
    unsigned long long r;
    asm("mov.b64 %0, {%1, %2};" : "=l"(r) : "f"(lo), "f"(hi));
    return r;
}
__device__ __forceinline__ void unpack2(unsigned long long v, float& lo, float& hi)
{
    asm("mov.b64 {%0, %1}, %2;" : "=f"(lo), "=f"(hi) : "l"(v));
}
__device__ __forceinline__ unsigned long long fma2(unsigned long long a,
                                                   unsigned long long b,
                                                   unsigned long long c)
{
    unsigned long long d;
    asm("fma.rn.f32x2 %0, %1, %2, %3;" : "=l"(d) : "l"(a), "l"(b), "l"(c));
    return d;
}

// ---------------------------------------------------------------------------
// 8-point complex FFT. s = +1: forward (e^{-i}), s = -1: inverse (e^{+i}),
// NO scaling. Fully unrolled, register-resident.
// ---------------------------------------------------------------------------
__device__ __forceinline__ void cfft8(float zr[8], float zi[8], const float s)
{
    const float cc = 0.70710678118654752440f;
    float t0r = zr[0] + zr[4], t0i = zi[0] + zi[4];
    float t1r = zr[0] - zr[4], t1i = zi[0] - zi[4];
    float t2r = zr[2] + zr[6], t2i = zi[2] + zi[6];
    float t3r = zr[2] - zr[6], t3i = zi[2] - zi[6];
    float E0r = t0r + t2r, E0i = t0i + t2i;
    float E2r = t0r - t2r, E2i = t0i - t2i;
    float E1r = t1r + s * t3i, E1i = t1i - s * t3r;
    float E3r = t1r - s * t3i, E3i = t1i + s * t3r;
    float u0r = zr[1] + zr[5], u0i = zi[1] + zi[5];
    float u1r = zr[1] - zr[5], u1i = zi[1] - zi[5];
    float u2r = zr[3] + zr[7], u2i = zi[3] + zi[7];
    float u3r = zr[3] - zr[7], u3i = zi[3] - zi[7];
    float O0r = u0r + u2r, O0i = u0i + u2i;
    float O2r = u0r - u2r, O2i = u0i - u2i;
    float O1r = u1r + s * u3i, O1i = u1i - s * u3r;
    float O3r = u1r - s * u3i, O3i = u1i + s * u3r;
    float T0r = O0r, T0i = O0i;
    float T1r = cc * (O1r + s * O1i), T1i = cc * (O1i - s * O1r);
    float T2r = s * O2i,              T2i = -s * O2r;
    float T3r = cc * (s * O3i - O3r), T3i = -cc * (O3i + s * O3r);
    zr[0] = E0r + T0r; zi[0] = E0i + T0i;
    zr[4] = E0r - T0r; zi[4] = E0i - T0i;
    zr[1] = E1r + T1r; zi[1] = E1i + T1i;
    zr[5] = E1r - T1r; zi[5] = E1i - T1i;
    zr[2] = E2r + T2r; zi[2] = E2i + T2i;
    zr[6] = E2r - T2r; zi[6] = E2i - T2i;
    zr[3] = E3r + T3r; zi[3] = E3i + T3i;
    zr[7] = E3r - T3r; zi[7] = E3i - T3i;
}

// ---------------------------------------------------------------------------
// Kernel G: 1x1 conv GEMM per patch (b,ph,pw): 256 out-channel slots x 64 px,
// k=64, f32x2 FMAs. Writes img_ / event_ as fp16 directly from registers.
// smem: sWT[64][256] + sIn[2][64][64] = 24576 floats = 98,304 B (2 blocks/SM)
// ---------------------------------------------------------------------------
__global__ void __launch_bounds__(256, 2) kG(const float* __restrict__ img,
                                             const float* __restrict__ evt,
                                             const float* __restrict__ w_img,
                                             const float* __restrict__ w_evt)
{
    extern __shared__ float sm[];
    float* sWT = sm;            // [64][256]
    float* sIn = sm + 16384;    // [2][64][64]

    const int tid = threadIdx.x;
    const int pw = blockIdx.x, ph = blockIdx.y, b = blockIdx.z;

    for (int i = tid; i < 64 * 128; i += 256) {
        int k = i >> 7, o = i & 127;
        sWT[k * 256 + o]       = w_img[o * 64 + k];
        sWT[k * 256 + 128 + o] = w_evt[o * 64 + k];
    }
    {
        const float4* img4 = reinterpret_cast<const float4*>(img);
        const float4* evt4 = reinterpret_cast<const float4*>(evt);
        for (int i = tid; i < 64 * 16; i += 256) {
            int c = i >> 4, q = i & 15;
            int r = q >> 1, h = q & 1;
            int g4 = (((b * 64 + c) * 256 + ph * 8 + r) * 256 + pw * 8) / 4 + h;
            *reinterpret_cast<float4*>(&sIn[c * 64 + q * 4])        = img4[g4];
            *reinterpret_cast<float4*>(&sIn[4096 + c * 64 + q * 4]) = evt4[g4];
        }
    }
    __syncthreads();

    const int rb = tid >> 3, cb = tid & 7;   // rb: channel block, cb: patch row
    const int r0 = rb * 8, c0 = cb * 8;
    const float* pin = sIn + ((r0 >= 128) ? 4096 : 0);

    unsigned long long acc[32];
#pragma unroll
    for (int i = 0; i < 32; i++) acc[i] = 0ULL;
#pragma unroll 8
    for (int k = 0; k < 64; k++) {
        float4 w0 = *reinterpret_cast<const float4*>(&sWT[k * 256 + r0]);
        float4 w1 = *reinterpret_cast<const float4*>(&sWT[k * 256 + r0 + 4]);
        ulonglong2 xa = *reinterpret_cast<const ulonglong2*>(&pin[k * 64 + c0]);
        ulonglong2 xb = *reinterpret_cast<const ulonglong2*>(&pin[k * 64 + c0 + 4]);
        unsigned long long xv[4] = {xa.x, xa.y, xb.x, xb.y};
        float wf[8] = {w0.x, w0.y, w0.z, w0.w, w1.x, w1.y, w1.z, w1.w};
#pragma unroll
        for (int i = 0; i < 8; i++) {
            unsigned long long wp = pack2(wf[i], wf[i]);
#pragma unroll
            for (int j = 0; j < 4; j++)
                acc[i * 4 + j] = fma2(wp, xv[j], acc[i * 4 + j]);
        }
    }

    // epilogue: fp16 stores, one 16B store per (channel, patch-row)
    __half* base = (r0 < 128) ? g_mid_i : g_mid_e;
    const int ch0 = r0 & 127;
    const int y = ph * 8 + cb, x = pw * 8;
#pragma unroll
    for (int i = 0; i < 8; i++) {
        __half2 h[4];
#pragma unroll
        for (int j = 0; j < 4; j++) {
            float lo, hi;
            unpack2(acc[i * 4 + j], lo, hi);
            h[j] = __floats2half2_rn(lo, hi);
        }
        size_t off = ((size_t)(b * 128 + ch0 + i) * 256 + y) * 256 + x;
        *reinterpret_cast<uint4*>(&base[off]) = *reinterpret_cast<uint4*>(h);
    }
}

// ---------------------------------------------------------------------------
// Kernel FFT: one thread = one (b, o, ph, pw) patch-channel. Entire pipeline
// register-resident: packed FFT of img + i*event, hermitian split, filter,
// X = (I+1)(f*E), inverse 2D FFT, fp32 store. Lane = pw -> coalesced I/O.
// ---------------------------------------------------------------------------
__global__ void __launch_bounds__(128, 2) kFFT(const float* __restrict__ filt)
{
    const int lane = threadIdx.x & 31;
    const int warp = threadIdx.x >> 5;
    const int pw = lane;
    const int ph = blockIdx.x * 4 + warp;
    const int o  = blockIdx.y;
    const int b  = blockIdx.z;

    const size_t pbase = (((size_t)(b * 128 + o) * 256 + ph * 8) * 256 + pw * 8);
    const __half* pi = g_mid_i + pbase;
    const __half* pe = g_mid_e + pbase;

    float Zr[64], Zi[64];

    // stage A: row FFTs of z = img_ + i*event_
#pragma unroll
    for (int r = 0; r < 8; r++) {
        uint4 ri = *reinterpret_cast<const uint4*>(pi + r * 256);
        uint4 re = *reinterpret_cast<const uint4*>(pe + r * 256);
        const __half2* hi2 = reinterpret_cast<const __half2*>(&ri);
        const __half2* he2 = reinterpret_cast<const __half2*>(&re);
        float zr[8], zi[8];
#pragma unroll
        for (int j = 0; j < 4; j++) {
            float2 a = __half22float2(hi2[j]);
            float2 c = __half22float2(he2[j]);
            zr[2 * j] = a.x; zr[2 * j + 1] = a.y;
            zi[2 * j] = c.x; zi[2 * j + 1] = c.y;
        }
        cfft8(zr, zi, 1.0f);
#pragma unroll
        for (int c = 0; c < 8; c++) { Zr[r * 8 + c] = zr[c]; Zi[r * 8 + c] = zi[c]; }
    }

    // stage B: column pairs (v, 8-v): fwd col FFTs, hermitian split, filter,
    // combine X=(I+1)(f*E), inverse col FFT, write back into column v.
    const float* fo = filt + o * 40;
    const int vv[5] = {0, 4, 1, 2, 3};
    const int mm[5] = {0, 4, 7, 6, 5};
#pragma unroll
    for (int pidx = 0; pidx < 5; pidx++) {
        const int v = vv[pidx], m = mm[pidx];
        float Pr[8], Pi[8], Qr[8], Qi[8];
#pragma unroll
        for (int u = 0; u < 8; u++) { Pr[u] = Zr[u * 8 + v]; Pi[u] = Zi[u * 8 + v]; }
        cfft8(Pr, Pi, 1.0f);
        if (m == v) {
#pragma unroll
            for (int u = 0; u < 8; u++) { Qr[u] = Pr[u]; Qi[u] = Pi[u]; }
        } else {
#pragma unroll
            for (int u = 0; u < 8; u++) { Qr[u] = Zr[u * 8 + m]; Qi[u] = Zi[u * 8 + m]; }
            cfft8(Qr, Qi, 1.0f);
        }
        float Xr[8], Xi[8];
#pragma unroll
        for (int u = 0; u < 8; u++) {
            int n = (8 - u) & 7;
            float pr = Pr[u], pi_ = Pi[u], qr = Qr[n], qi = Qi[n];
            float Ir = 0.5f * (pr + qr), Ii = 0.5f * (pi_ - qi);
            float f  = fo[u * 5 + v];
            float Er = 0.5f * f * (pi_ + qi), Ei = 0.5f * f * (qr - pr);
            float ar = Ir + 1.0f;
            Xr[u] = ar * Er - Ii * Ei;
            Xi[u] = ar * Ei + Ii * Er;
        }
        cfft8(Xr, Xi, -1.0f);
#pragma unroll
        for (int r = 0; r < 8; r++) { Zr[r * 8 + v] = Xr[r]; Zi[r * 8 + v] = Xi[r]; }
    }

    // stage C: row inverse (hermitian extension over v), scale 1/64, store
    float* outp = g_xmid + pbase;
    const float sc = 1.0f / 64.0f;
#pragma unroll
    for (int r = 0; r < 8; r++) {
        float zr[8], zi[8];
#pragma unroll
        for (int v = 0; v < 5; v++) { zr[v] = Zr[r * 8 + v]; zi[v] = Zi[r * 8 + v]; }
        zr[5] = zr[3]; zi[5] = -zi[3];
        zr[6] = zr[2]; zi[6] = -zi[2];
        zr[7] = zr[1]; zi[7] = -zi[1];
        cfft8(zr, zi, -1.0f);
        float4 o0 = {zr[0] * sc, zr[1] * sc, zr[2] * sc, zr[3] * sc};
        float4 o1 = {zr[4] * sc, zr[5] * sc, zr[6] * sc, zr[7] * sc};
        *reinterpret_cast<float4*>(&outp[r * 256])     = o0;
        *reinterpret_cast<float4*>(&outp[r * 256 + 4]) = o1;
    }
}

// ---------------------------------------------------------------------------
// Kernel DW: depthwise 3x3 (SAME) on channel pair (c, c+64), exact GELU gate.
// Block = 64x16 pixel tile of one (b, c). One halo load, one sync.
// ---------------------------------------------------------------------------
__global__ void __launch_bounds__(256) kDW(const float* __restrict__ w_dw)
{
    __shared__ float sH[2 * 18 * 68];   // [2][18][68] padded rows

    const int tid = threadIdx.x;
    const int b = blockIdx.z >> 6, c = blockIdx.z & 63;
    const int x0 = blockIdx.x * 64, y0 = blockIdx.y * 16;

    float w1[9], w2[9];
#pragma unroll
    for (int j = 0; j < 9; j++) {
        w1[j] = w_dw[c * 9 + j];
        w2[j] = w_dw[(c + 64) * 9 + j];
    }

    const float* src0 = g_xmid + (size_t)(b * 128 + c) * 65536;
    const float* src1 = src0 + (size_t)64 * 65536;

    for (int i = tid; i < 18 * 66; i += 256) {
        int y = i / 66, x = i - y * 66;
        int gy = y0 + y - 1, gx = x0 + x - 1;
        float v0 = 0.f, v1 = 0.f;
        if (gy >= 0 && gy < 256 && gx >= 0 && gx < 256) {
            size_t gi = (size_t)gy * 256 + gx;
            v0 = src0[gi];
            v1 = src1[gi];
        }
        sH[y * 68 + x]        = v0;
        sH[1224 + y * 68 + x] = v1;
    }
    __syncthreads();

    const int px = tid & 63, ty = tid >> 6;
    float* dst = g_gate + (size_t)(b * 64 + c) * 65536;
#pragma unroll
    for (int yy = 0; yy < 4; yy++) {
        int py = ty * 4 + yy;
        float a = 0.f, bb = 0.f;
#pragma unroll
        for (int dy = 0; dy < 3; dy++)
#pragma unroll
            for (int dx = 0; dx < 3; dx++) {
                a  = fmaf(sH[(py + dy) * 68 + px + dx],        w1[dy * 3 + dx], a);
                bb = fmaf(sH[1224 + (py + dy) * 68 + px + dx], w2[dy * 3 + dx], bb);
            }
        float gl = 0.5f * a * (1.0f + erff(a * 0.70710678118654752f));
        dst[(size_t)(y0 + py) * 256 + x0 + px] = gl * bb;
    }
}

// ---------------------------------------------------------------------------
// Kernel Out: 1x1 projection. Block = one image row (256 px), all 64 k.
// GEMM 64oc x 256px x 64k, thread tile 8x8, f32x2 FMAs.
// smem: sG[64][256]=16384 | sWoT[64][64]=4096  -> 81,920 B (2 blocks/SM)
// ---------------------------------------------------------------------------
__global__ void __launch_bounds__(256, 2) kOut(const float* __restrict__ w_out,
                                               float* __restrict__ out)
{
    extern __shared__ float sm[];
    float* sG   = sm;          // [64][256]
    float* sWoT = sm + 16384;  // [64][64]

    const int tid = threadIdx.x;
    const int y = blockIdx.x, b = blockIdx.y;

    for (int i = tid; i < 64 * 64; i += 256) {
        int k = i >> 6, o = i & 63;
        sWoT[k * 64 + o] = w_out[o * 64 + k];
    }
    for (int i = tid; i < 64 * 256; i += 256) {
        int k = i >> 8, p = i & 255;
        sG[i] = g_gate[(size_t)(b * 64 + k) * 65536 + (size_t)y * 256 + p];
    }
    __syncthreads();

    const int ob = tid >> 5, pb = tid & 31;
    const int oc0 = ob * 8, p0 = pb * 8;
    unsigned long long acc[32];
#pragma unroll
    for (int i = 0; i < 32; i++) acc[i] = 0ULL;
#pragma unroll 8
    for (int k = 0; k < 64; k++) {
        float4 w0 = *reinterpret_cast<const float4*>(&sWoT[k * 64 + oc0]);
        float4 w1 = *reinterpret_cast<const float4*>(&sWoT[k * 64 + oc0 + 4]);
        ulonglong2 ga = *reinterpret_cast<const ulonglong2*>(&sG[k * 256 + p0]);
        ulonglong2 gb = *reinterpret_cast<const ulonglong2*>(&sG[k * 256 + p0 + 4]);
        unsigned long long gv[4] = {ga.x, ga.y, gb.x, gb.y};
        float wf[8] = {w0.x, w0.y, w0.z, w0.w, w1.x, w1.y, w1.z, w1.w};
#pragma unroll
        for (int i = 0; i < 8; i++) {
            unsigned long long wp = pack2(wf[i], wf[i]);
#pragma unroll
            for (int j = 0; j < 4; j++)
                acc[i * 4 + j] = fma2(wp, gv[j], acc[i * 4 + j]);
        }
    }
#pragma unroll
    for (int i = 0; i < 8; i++) {
        float v[8];
#pragma unroll
        for (int j = 0; j < 4; j++) unpack2(acc[i * 4 + j], v[2 * j], v[2 * j + 1]);
        size_t ga = ((size_t)(b * 64 + oc0 + i) * 256 + y) * 256 + p0;
        float4 q0 = {v[0], v[1], v[2], v[3]};
        float4 q1 = {v[4], v[5], v[6], v[7]};
        *reinterpret_cast<float4*>(&out[ga])     = q0;
        *reinterpret_cast<float4*>(&out[ga + 4]) = q1;
    }
}

// ---------------------------------------------------------------------------
extern "C" void kernel_launch(void* const* d_in, const int* in_sizes, int n_in,
                              void* d_out, int out_size)
{
    const float* img   = (const float*)d_in[0];
    const float* evt   = (const float*)d_in[1];
    const float* w_img = (const float*)d_in[2];
    const float* w_evt = (const float*)d_in[3];
    const float* w_dw  = (const float*)d_in[4];
    const float* filt  = (const float*)d_in[5];
    const float* w_out = (const float*)d_in[6];
    float* out = (float*)d_out;

    const int smemG = 24576 * 4;   // 98,304 B -> 2 blocks/SM
    const int smemO = 20480 * 4;   // 81,920 B -> 2 blocks/SM
    cudaFuncSetAttribute(kG,   cudaFuncAttributeMaxDynamicSharedMemorySize, smemG);
    cudaFuncSetAttribute(kOut, cudaFuncAttributeMaxDynamicSharedMemorySize, smemO);

    kG<<<dim3(32, 32, 4), 256, smemG>>>(img, evt, w_img, w_evt);
    kFFT<<<dim3(8, 128, 4), 128>>>(filt);
    kDW<<<dim3(4, 16, 256), 256>>>(w_dw);
    kOut<<<dim3(256, 4), 256, smemO>>>(w_out, out);
}

// round 7
// speedup vs baseline: 1.6569x; 1.0676x over previous
#include <cuda_runtime.h>
#include <cuda_fp16.h>
#include <cstdint>
#include <cmath>

// scratch: mid tensor x [4,128,256,256] fp16, gated tensor [4,64,256,256] fp32
static __device__ __align__(16) __half g_xmid[(size_t)4 * 128 * 256 * 256];
static __device__ __align__(16) float  g_gate[(size_t)4 * 64 * 256 * 256];

// ---------------------------------------------------------------------------
// f32x2 packed helpers (Blackwell FFMA2 path — only reachable via PTX)
// ---------------------------------------------------------------------------
__device__ __forceinline__ unsigned long long pack2(float lo, float hi)
{
    unsigned long long r;
    asm("mov.b64 %0, {%1, %2};" : "=l"(r) : "f"(lo), "f"(hi));
    return r;
}
__device__ __forceinline__ void unpack2(unsigned long long v, float& lo, float& hi)
{
    asm("mov.b64 {%0, %1}, %2;" : "=f"(lo), "=f"(hi) : "l"(v));
}
__device__ __forceinline__ unsigned long long fma2(unsigned long long a,
                                                   unsigned long long b,
                                                   unsigned long long c)
{
    unsigned long long d;
    asm("fma.rn.f32x2 %0, %1, %2, %3;" : "=l"(d) : "l"(a), "l"(b), "l"(c));
    return d;
}

// ---------------------------------------------------------------------------
// 8-point complex FFT (single thread). s=+1 forward (e^{-i}), s=-1 inverse
// (e^{+i}), NO scaling.
// ---------------------------------------------------------------------------
__device__ __forceinline__ void cfft8(float zr[8], float zi[8], const float s)
{
    const float cc = 0.70710678118654752440f;
    float t0r = zr[0] + zr[4], t0i = zi[0] + zi[4];
    float t1r = zr[0] - zr[4], t1i = zi[0] - zi[4];
    float t2r = zr[2] + zr[6], t2i = zi[2] + zi[6];
    float t3r = zr[2] - zr[6], t3i = zi[2] - zi[6];
    float E0r = t0r + t2r, E0i = t0i + t2i;
    float E2r = t0r - t2r, E2i = t0i - t2i;
    float E1r = t1r + s * t3i, E1i = t1i - s * t3r;
    float E3r = t1r - s * t3i, E3i = t1i + s * t3r;
    float u0r = zr[1] + zr[5], u0i = zi[1] + zi[5];
    float u1r = zr[1] - zr[5], u1i = zi[1] - zi[5];
    float u2r = zr[3] + zr[7], u2i = zi[3] + zi[7];
    float u3r = zr[3] - zr[7], u3i = zi[3] - zi[7];
    float O0r = u0r + u2r, O0i = u0i + u2i;
    float O2r = u0r - u2r, O2i = u0i - u2i;
    float O1r = u1r + s * u3i, O1i = u1i - s * u3r;
    float O3r = u1r - s * u3i, O3i = u1i + s * u3r;
    float T0r = O0r, T0i = O0i;
    float T1r = cc * (O1r + s * O1i), T1i = cc * (O1i - s * O1r);
    float T2r = s * O2i,              T2i = -s * O2r;
    float T3r = cc * (s * O3i - O3r), T3i = -cc * (O3i + s * O3r);
    zr[0] = E0r + T0r; zi[0] = E0i + T0i;
    zr[4] = E0r - T0r; zi[4] = E0i - T0i;
    zr[1] = E1r + T1r; zi[1] = E1i + T1i;
    zr[5] = E1r - T1r; zi[5] = E1i - T1i;
    zr[2] = E2r + T2r; zi[2] = E2i + T2i;
    zr[6] = E2r - T2r; zi[6] = E2i - T2i;
    zr[3] = E3r + T3r; zi[3] = E3i + T3i;
    zr[7] = E3r - T3r; zi[7] = E3i - T3i;
}

// ---------------------------------------------------------------------------
// Kernel F2 (512 threads, fused): per 2-patch tile (b, ph, pw16):
//   phase 1: 1x1 conv GEMM 256 slots x 128 px (k=64), f32x2, acc in regs
//   phase 2: spill to sMid (aliases dead sWT/sIn), then cooperative
//            register-resident packed FFT: 2 threads per (channel, patch),
//            row-halves split, columns via one shfl.xor(16) DIF/DIT stage.
// smem: phase1 sWT[64][256] + sIn[2][64][128] = 32768 fl
//       phase2 sMid[256][132] = 33792 fl  (alias)  -> 135,168 B
// ---------------------------------------------------------------------------
__global__ void __launch_bounds__(512, 1) kF2(const float* __restrict__ img,
                                              const float* __restrict__ evt,
                                              const float* __restrict__ w_img,
                                              const float* __restrict__ w_evt,
                                              const float* __restrict__ filt)
{
    extern __shared__ float sm[];
    float* sWT  = sm;            // [64][256]
    float* sIn  = sm + 16384;    // [2][64][128]
    float* sMid = sm;            // [256][132] alias

    const int tid = threadIdx.x;
    const int pw = blockIdx.x, ph = blockIdx.y, b = blockIdx.z;

    // weights transposed: sWT[k][slot] (slot<128: img oc, >=128: event oc)
    for (int i = tid; i < 64 * 128; i += 512) {
        int k = i >> 7, o = i & 127;
        sWT[k * 256 + o]       = w_img[o * 64 + k];
        sWT[k * 256 + 128 + o] = w_evt[o * 64 + k];
    }
    // pixels: 2 adjacent patches = rows ph*8.., cols pw*16..+15
    {
        const float4* img4 = reinterpret_cast<const float4*>(img);
        const float4* evt4 = reinterpret_cast<const float4*>(evt);
        for (int i = tid; i < 64 * 32; i += 512) {
            int c = i >> 5, q4 = i & 31;
            int r = q4 >> 2, xx = q4 & 3;
            int g4 = (((b * 64 + c) * 256 + ph * 8 + r) * 256 + pw * 16) / 4 + xx;
            *reinterpret_cast<float4*>(&sIn[c * 128 + q4 * 4])        = img4[g4];
            *reinterpret_cast<float4*>(&sIn[8192 + c * 128 + q4 * 4]) = evt4[g4];
        }
    }
    __syncthreads();

    // GEMM: 256 slots x 128 px, k=64; thread tile 8 slots x 8 px (f32x2)
    unsigned long long acc[32];
#pragma unroll
    for (int i = 0; i < 32; i++) acc[i] = 0ULL;
    const int rb = tid >> 4, cb = tid & 15;
    const int r0 = rb * 8, c0 = cb * 8;
    {
        const float* pin = sIn + ((r0 >= 128) ? 8192 : 0);
#pragma unroll 4
        for (int k = 0; k < 64; k++) {
            float4 w0 = *reinterpret_cast<const float4*>(&sWT[k * 256 + r0]);
            float4 w1 = *reinterpret_cast<const float4*>(&sWT[k * 256 + r0 + 4]);
            ulonglong2 xa = *reinterpret_cast<const ulonglong2*>(&pin[k * 128 + c0]);
            ulonglong2 xb = *reinterpret_cast<const ulonglong2*>(&pin[k * 128 + c0 + 4]);
            unsigned long long xv[4] = {xa.x, xa.y, xb.x, xb.y};
            float wf[8] = {w0.x, w0.y, w0.z, w0.w, w1.x, w1.y, w1.z, w1.w};
#pragma unroll
            for (int i = 0; i < 8; i++) {
                unsigned long long wp = pack2(wf[i], wf[i]);
#pragma unroll
                for (int j = 0; j < 4; j++)
                    acc[i * 4 + j] = fma2(wp, xv[j], acc[i * 4 + j]);
            }
        }
    }
    __syncthreads();   // sWT/sIn dead -> region becomes sMid

    // spill acc -> sMid [256][132]
#pragma unroll
    for (int i = 0; i < 8; i++)
#pragma unroll
        for (int j = 0; j < 4; j++) {
            float lo, hi;
            unpack2(acc[i * 4 + j], lo, hi);
            *reinterpret_cast<float2*>(&sMid[(r0 + i) * 132 + c0 + 2 * j]) =
                make_float2(lo, hi);
        }
    __syncthreads();

    // ---- phase 2: cooperative FFT. warp w, lane l: h = l>>4 (row half),
    // item = w*16 + (l&15): o = item & 127 (channel), pp = item >> 7 (patch).
    {
        const int lane = tid & 31;
        const int w    = tid >> 5;
        const int h    = lane >> 4;              // 0: rows 0-3, 1: rows 4-7
        const int item = w * 16 + (lane & 15);
        const int o    = item & 127;
        const int pp   = item >> 7;
        const bool hB  = (h == 1);
        const float C7 = 0.70710678118654752440f;

        const float* rowI = sMid + o * 132 + pp * 8;
        const float* rowE = sMid + (128 + o) * 132 + pp * 8;

        float Zr[32], Zi[32];   // local 4 rows x 8 cols

        // stage A: row FFTs of z = img + i*event (rows h*4 .. h*4+3)
#pragma unroll
        for (int j = 0; j < 4; j++) {
            const int R = h * 4 + j;
            float zr[8], zi[8];
            float4 a0 = *reinterpret_cast<const float4*>(rowI + R * 16);
            float4 a1 = *reinterpret_cast<const float4*>(rowI + R * 16 + 4);
            float4 b0 = *reinterpret_cast<const float4*>(rowE + R * 16);
            float4 b1 = *reinterpret_cast<const float4*>(rowE + R * 16 + 4);
            zr[0]=a0.x; zr[1]=a0.y; zr[2]=a0.z; zr[3]=a0.w;
            zr[4]=a1.x; zr[5]=a1.y; zr[6]=a1.z; zr[7]=a1.w;
            zi[0]=b0.x; zi[1]=b0.y; zi[2]=b0.z; zi[3]=b0.w;
            zi[4]=b1.x; zi[5]=b1.y; zi[6]=b1.z; zi[7]=b1.w;
            cfft8(zr, zi, 1.0f);
#pragma unroll
            for (int c = 0; c < 8; c++) { Zr[j * 8 + c] = zr[c]; Zi[j * 8 + c] = zi[c]; }
        }

        // stage B-fwd: 8-pt column FFTs, DIF split across thread pair.
        // After: Z[k][c] = F_{2k+h}(column c).
#pragma unroll
        for (int c = 0; c < 8; c++) {
            float lr[4], li[4], rr[4], ri[4];
#pragma unroll
            for (int j = 0; j < 4; j++) { lr[j] = Zr[j * 8 + c]; li[j] = Zi[j * 8 + c]; }
#pragma unroll
            for (int j = 0; j < 4; j++) {
                rr[j] = __shfl_xor_sync(0xffffffffu, lr[j], 16);
                ri[j] = __shfl_xor_sync(0xffffffffu, li[j], 16);
            }
            float tr[4], ti[4];
            if (!hB) {   // a_j = z_j + z_{j+4}
#pragma unroll
                for (int j = 0; j < 4; j++) { tr[j] = lr[j] + rr[j]; ti[j] = li[j] + ri[j]; }
            } else {     // b_j = (z_j - z_{j+4}) * W8^j,  W8^j = e^{-i pi j/4}
                float dr[4], di[4];
#pragma unroll
                for (int j = 0; j < 4; j++) { dr[j] = rr[j] - lr[j]; di[j] = ri[j] - li[j]; }
                tr[0] = dr[0];               ti[0] = di[0];
                tr[1] = C7 * (dr[1] + di[1]); ti[1] = C7 * (di[1] - dr[1]);
                tr[2] = di[2];               ti[2] = -dr[2];
                tr[3] = C7 * (di[3] - dr[3]); ti[3] = -C7 * (dr[3] + di[3]);
            }
            // forward FFT4 (e^{-i})
            float s0r = tr[0] + tr[2], s0i = ti[0] + ti[2];
            float s1r = tr[0] - tr[2], s1i = ti[0] - ti[2];
            float s2r = tr[1] + tr[3], s2i = ti[1] + ti[3];
            float s3r = tr[1] - tr[3], s3i = ti[1] - ti[3];
            Zr[0 * 8 + c] = s0r + s2r; Zi[0 * 8 + c] = s0i + s2i;
            Zr[1 * 8 + c] = s1r + s3i; Zi[1 * 8 + c] = s1i - s3r;  // s1 - i*s3
            Zr[2 * 8 + c] = s0r - s2r; Zi[2 * 8 + c] = s0i - s2i;
            Zr[3 * 8 + c] = s1r - s3i; Zi[3 * 8 + c] = s1i + s3r;  // s1 + i*s3
        }

        // stage B-combine+inverse: pairs (v, m=(8-v)&7). Parity of n=(8-u)&7
        // matches u, so hermitian partner bins are thread-local.
        const float* fo = filt + o * 40;
        const int vv[5] = {0, 4, 1, 2, 3};
        const int mm[5] = {0, 4, 7, 6, 5};
#pragma unroll
        for (int pidx = 0; pidx < 5; pidx++) {
            const int v = vv[pidx], m = mm[pidx];
            float xr[4], xi[4];
#pragma unroll
            for (int k = 0; k < 4; k++) {
                const int u  = 2 * k + h;
                const int kn = hB ? (3 - k) : ((4 - k) & 3);
                float pr = Zr[k * 8 + v],  pi_ = Zi[k * 8 + v];
                float qr = Zr[kn * 8 + m], qi  = Zi[kn * 8 + m];
                float Ir = 0.5f * (pr + qr), Ii = 0.5f * (pi_ - qi);
                float f  = fo[u * 5 + v];
                float Er = 0.5f * f * (pi_ + qi), Ei = 0.5f * f * (qr - pr);
                float ar = Ir + 1.0f;
                xr[k] = ar * Er - Ii * Ei;
                xi[k] = ar * Ei + Ii * Er;
            }
            // IFFT4 (e^{+i}, unscaled)
            float s0r = xr[0] + xr[2], s0i = xi[0] + xi[2];
            float s1r = xr[0] - xr[2], s1i = xi[0] - xi[2];
            float s2r = xr[1] + xr[3], s2i = xi[1] + xi[3];
            float s3r = xr[1] - xr[3], s3i = xi[1] - xi[3];
            float gr[4], gi[4];
            gr[0] = s0r + s2r; gi[0] = s0i + s2i;
            gr[1] = s1r - s3i; gi[1] = s1i + s3r;   // s1 + i*s3
            gr[2] = s0r - s2r; gi[2] = s0i - s2i;
            gr[3] = s1r + s3i; gi[3] = s1i - s3r;   // s1 - i*s3
            float hr[4], hi[4];
#pragma unroll
            for (int j = 0; j < 4; j++) {
                hr[j] = __shfl_xor_sync(0xffffffffu, gr[j], 16);
                hi[j] = __shfl_xor_sync(0xffffffffu, gi[j], 16);
            }
            // combine with W8^{-j} = e^{+i pi j/4}: (1,0),(c,c),(0,1),(-c,c)
            if (!hB) {   // z_j = G_j + W^{-j} H_j   (H = odd part)
                Zr[0*8+v] = gr[0] + hr[0];                 Zi[0*8+v] = gi[0] + hi[0];
                Zr[1*8+v] = gr[1] + C7 * (hr[1] - hi[1]);  Zi[1*8+v] = gi[1] + C7 * (hr[1] + hi[1]);
                Zr[2*8+v] = gr[2] - hi[2];                 Zi[2*8+v] = gi[2] + hr[2];
                Zr[3*8+v] = gr[3] - C7 * (hr[3] + hi[3]);  Zi[3*8+v] = gi[3] + C7 * (hr[3] - hi[3]);
            } else {     // z_{j+4} = H_j - W^{-j} G_j  (H = even part, G = odd local)
                Zr[0*8+v] = hr[0] - gr[0];                 Zi[0*8+v] = hi[0] - gi[0];
                Zr[1*8+v] = hr[1] - C7 * (gr[1] - gi[1]);  Zi[1*8+v] = hi[1] - C7 * (gr[1] + gi[1]);
                Zr[2*8+v] = hr[2] + gi[2];                 Zi[2*8+v] = hi[2] - gr[2];
                Zr[3*8+v] = hr[3] + C7 * (gr[3] + gi[3]);  Zi[3*8+v] = hi[3] - C7 * (gr[3] - gi[3]);
            }
        }

        // stage C: row inverse (hermitian extension over v), 1/64, fp16 store
        __half* outp = g_xmid + (((size_t)(b * 128 + o) * 256 + ph * 8) * 256
                                 + pw * 16 + pp * 8);
        const float sc = 1.0f / 64.0f;
#pragma unroll
        for (int j = 0; j < 4; j++) {
            const int R = h * 4 + j;
            float zr[8], zi[8];
#pragma unroll
            for (int v = 0; v < 5; v++) { zr[v] = Zr[j * 8 + v]; zi[v] = Zi[j * 8 + v]; }
            zr[5] = Zr[j * 8 + 3]; zi[5] = -Zi[j * 8 + 3];
            zr[6] = Zr[j * 8 + 2]; zi[6] = -Zi[j * 8 + 2];
            zr[7] = Zr[j * 8 + 1]; zi[7] = -Zi[j * 8 + 1];
            cfft8(zr, zi, -1.0f);
            __half2 hh[4];
#pragma unroll
            for (int t = 0; t < 4; t++)
                hh[t] = __floats2half2_rn(zr[2 * t] * sc, zr[2 * t + 1] * sc);
            *reinterpret_cast<uint4*>(outp + (size_t)R * 256) =
                *reinterpret_cast<uint4*>(hh);
        }
    }
}

// ---------------------------------------------------------------------------
// Kernel DW: depthwise 3x3 (SAME) on channel pair (c, c+64), exact GELU gate.
// Block = 64x16 pixel tile of one (b, c). Reads fp16 xmid.
// ---------------------------------------------------------------------------
__global__ void __launch_bounds__(256) kDW(const float* __restrict__ w_dw)
{
    __shared__ float sH[2 * 18 * 68];

    const int tid = threadIdx.x;
    const int b = blockIdx.z >> 6, c = blockIdx.z & 63;
    const int x0 = blockIdx.x * 64, y0 = blockIdx.y * 16;

    float w1[9], w2[9];
#pragma unroll
    for (int j = 0; j < 9; j++) {
        w1[j] = w_dw[c * 9 + j];
        w2[j] = w_dw[(c + 64) * 9 + j];
    }

    const __half* src0 = g_xmid + (size_t)(b * 128 + c) * 65536;
    const __half* src1 = src0 + (size_t)64 * 65536;

    for (int i = tid; i < 18 * 66; i += 256) {
        int y = i / 66, x = i - y * 66;
        int gy = y0 + y - 1, gx = x0 + x - 1;
        float v0 = 0.f, v1 = 0.f;
        if (gy >= 0 && gy < 256 && gx >= 0 && gx < 256) {
            size_t gi = (size_t)gy * 256 + gx;
            v0 = __half2float(src0[gi]);
            v1 = __half2float(src1[gi]);
        }
        sH[y * 68 + x]        = v0;
        sH[1224 + y * 68 + x] = v1;
    }
    __syncthreads();

    const int px = tid & 63, ty = tid >> 6;
    float* dst = g_gate + (size_t)(b * 64 + c) * 65536;
#pragma unroll
    for (int yy = 0; yy < 4; yy++) {
        int py = ty * 4 + yy;
        float a = 0.f, bb = 0.f;
#pragma unroll
        for (int dy = 0; dy < 3; dy++)
#pragma unroll
            for (int dx = 0; dx < 3; dx++) {
                a  = fmaf(sH[(py + dy) * 68 + px + dx],        w1[dy * 3 + dx], a);
                bb = fmaf(sH[1224 + (py + dy) * 68 + px + dx], w2[dy * 3 + dx], bb);
            }
        float gl = 0.5f * a * (1.0f + erff(a * 0.70710678118654752f));
        dst[(size_t)(y0 + py) * 256 + x0 + px] = gl * bb;
    }
}

// ---------------------------------------------------------------------------
// Kernel Out: 1x1 projection. Block = one image row (256 px), all 64 k.
// GEMM 64oc x 256px x 64k, thread tile 8x8, f32x2 FMAs. float4 gate loads.
// ---------------------------------------------------------------------------
__global__ void __launch_bounds__(256, 2) kOut(const float* __restrict__ w_out,
                                               float* __restrict__ out)
{
    extern __shared__ float sm[];
    float* sG   = sm;          // [64][256]
    float* sWoT = sm + 16384;  // [64][64]

    const int tid = threadIdx.x;
    const int y = blockIdx.x, b = blockIdx.y;

    for (int i = tid; i < 64 * 64; i += 256) {
        int k = i >> 6, o = i & 63;
        sWoT[k * 64 + o] = w_out[o * 64 + k];
    }
    {
        const float4* gate4 = reinterpret_cast<const float4*>(g_gate);
        for (int i = tid; i < 64 * 64; i += 256) {
            int k = i >> 6, p4 = i & 63;
            *reinterpret_cast<float4*>(&sG[k * 256 + p4 * 4]) =
                gate4[((size_t)(b * 64 + k) * 65536 + (size_t)y * 256) / 4 + p4];
        }
    }
    __syncthreads();

    const int ob = tid >> 5, pb = tid & 31;
    const int oc0 = ob * 8, p0 = pb * 8;
    unsigned long long acc[32];
#pragma unroll
    for (int i = 0; i < 32; i++) acc[i] = 0ULL;
#pragma unroll 8
    for (int k = 0; k < 64; k++) {
        float4 w0 = *reinterpret_cast<const float4*>(&sWoT[k * 64 + oc0]);
        float4 w1 = *reinterpret_cast<const float4*>(&sWoT[k * 64 + oc0 + 4]);
        ulonglong2 ga = *reinterpret_cast<const ulonglong2*>(&sG[k * 256 + p0]);
        ulonglong2 gb = *reinterpret_cast<const ulonglong2*>(&sG[k * 256 + p0 + 4]);
        unsigned long long gv[4] = {ga.x, ga.y, gb.x, gb.y};
        float wf[8] = {w0.x, w0.y, w0.z, w0.w, w1.x, w1.y, w1.z, w1.w};
#pragma unroll
        for (int i = 0; i < 8; i++) {
            unsigned long long wp = pack2(wf[i], wf[i]);
#pragma unroll
            for (int j = 0; j < 4; j++)
                acc[i * 4 + j] = fma2(wp, gv[j], acc[i * 4 + j]);
        }
    }
#pragma unroll
    for (int i = 0; i < 8; i++) {
        float v[8];
#pragma unroll
        for (int j = 0; j < 4; j++) unpack2(acc[i * 4 + j], v[2 * j], v[2 * j + 1]);
        size_t ga = ((size_t)(b * 64 + oc0 + i) * 256 + y) * 256 + p0;
        float4 q0 = {v[0], v[1], v[2], v[3]};
        float4 q1 = {v[4], v[5], v[6], v[7]};
        *reinterpret_cast<float4*>(&out[ga])     = q0;
        *reinterpret_cast<float4*>(&out[ga + 4]) = q1;
    }
}

// ---------------------------------------------------------------------------
extern "C" void kernel_launch(void* const* d_in, const int* in_sizes, int n_in,
                              void* d_out, int out_size)
{
    const float* img   = (const float*)d_in[0];
    const float* evt   = (const float*)d_in[1];
    const float* w_img = (const float*)d_in[2];
    const float* w_evt = (const float*)d_in[3];
    const float* w_dw  = (const float*)d_in[4];
    const float* filt  = (const float*)d_in[5];
    const float* w_out = (const float*)d_in[6];
    float* out = (float*)d_out;

    const int smemF = 33792 * 4;   // 135,168 B
    const int smemO = 20480 * 4;   //  81,920 B
    cudaFuncSetAttribute(kF2,  cudaFuncAttributeMaxDynamicSharedMemorySize, smemF);
    cudaFuncSetAttribute(kOut, cudaFuncAttributeMaxDynamicSharedMemorySize, smemO);

    kF2<<<dim3(16, 32, 4), 512, smemF>>>(img, evt, w_img, w_evt, filt);
    kDW<<<dim3(4, 16, 256), 256>>>(w_dw);
    kOut<<<dim3(256, 4), 256, smemO>>>(w_out, out);
}